// round 14
// baseline (speedup 1.0000x reference)
#include <cuda_runtime.h>
#include <cuda_fp16.h>
#include <math.h>
#include <stdint.h>

// Problem constants
#define B_  8
#define S_  1024
#define D_  256
#define H_  8
#define DH_ 32
#define L_  4
#define V_  100
#define DFF_ 1024
#define M_TOK (B_ * S_)   // 8192
#define QKV_N 768

#define SCL2E 0.2550348243f   // log2(e)/sqrt(32)

// -------- scratch (static device globals; no runtime allocation) --------
__device__ float g_x [M_TOK * D_];

__device__ __half g_xh  [M_TOK * D_],  g_xl[M_TOK * D_];
__device__ __half g_yh  [M_TOK * D_];
__device__ __half g_ffh [M_TOK * DFF_];
__device__ __half g_qkvh[M_TOK * QKV_N];

__device__ __half g_qkvT[L_*QKV_N*D_];
__device__ __half g_oT  [L_*D_*D_];
__device__ __half g_1T  [L_*DFF_*D_];
__device__ __half g_2T  [L_*D_*DFF_];
__device__ __half g_cT_hi[128*D_], g_cT_lo[128*D_];
__device__ float g_bqkv[L_ * QKV_N];

// =========================== PTX helpers ==================================
__device__ __forceinline__ uint32_t smem_u32(const void* p) {
    uint32_t r;
    asm("{ .reg .u64 t; cvta.to.shared.u64 t, %1; cvt.u32.u64 %0, t; }"
        : "=r"(r) : "l"(p));
    return r;
}
__device__ __forceinline__ void cp_async16(uint32_t dst, const void* src) {
    asm volatile("cp.async.cg.shared.global [%0], [%1], 16;"
                 :: "r"(dst), "l"(src));
}
__device__ __forceinline__ void cp_commit() {
    asm volatile("cp.async.commit_group;" ::: "memory");
}
__device__ __forceinline__ void cp_wait1() {
    asm volatile("cp.async.wait_group 1;" ::: "memory");
}
__device__ __forceinline__ void cp_wait0() {
    asm volatile("cp.async.wait_group 0;" ::: "memory");
}
__device__ __forceinline__ void ldsm_x4(uint32_t* r, uint32_t addr) {
    asm volatile("ldmatrix.sync.aligned.m8n8.x4.shared.b16 {%0,%1,%2,%3}, [%4];"
                 : "=r"(r[0]), "=r"(r[1]), "=r"(r[2]), "=r"(r[3]) : "r"(addr));
}
__device__ __forceinline__ void ldsm_x4t(uint32_t* r, uint32_t addr) {
    asm volatile("ldmatrix.sync.aligned.m8n8.x4.trans.shared.b16 {%0,%1,%2,%3}, [%4];"
                 : "=r"(r[0]), "=r"(r[1]), "=r"(r[2]), "=r"(r[3]) : "r"(addr));
}
__device__ __forceinline__ void mma_f16(float* d, const uint32_t* a,
                                        uint32_t b0, uint32_t b1) {
    asm volatile(
        "mma.sync.aligned.m16n8k16.row.col.f32.f16.f16.f32 "
        "{%0,%1,%2,%3}, {%4,%5,%6,%7}, {%8,%9}, {%0,%1,%2,%3};"
        : "+f"(d[0]), "+f"(d[1]), "+f"(d[2]), "+f"(d[3])
        : "r"(a[0]), "r"(a[1]), "r"(a[2]), "r"(a[3]), "r"(b0), "r"(b1));
}
__device__ __forceinline__ uint32_t swz128(uint32_t x) {
    return x ^ ((x >> 3) & 0x70u);
}
__device__ __forceinline__ uint32_t pack_h2(__half a, __half b) {
    __half2 t(a, b);
    return *reinterpret_cast<uint32_t*>(&t);
}
__device__ __forceinline__ uint32_t pack_f2h(float a, float b) {
    __half2 t = __floats2half2_rn(a, b);
    return *reinterpret_cast<uint32_t*>(&t);
}
__device__ __forceinline__ void split2h(float a, float b, uint32_t& hi, uint32_t& lo) {
    __half h0 = __float2half_rn(a);
    __half h1 = __float2half_rn(b);
    __half l0 = __float2half_rn(a - __half2float(h0));
    __half l1 = __float2half_rn(b - __half2float(h1));
    hi = pack_h2(h0, h1);
    lo = pack_h2(l0, l1);
}

// ===================== GEMM tiling constants ==============================
#define GBM 128
#define GBN 64
#define GKB 64
#define APLANE 16384
#define BPLANE 8192
#define BUFB (APLANE + BPLANE)
#define GEMM_SMEM (3*BUFB + 1024)
#define CLS_BUFB (2*APLANE + 2*BPLANE)
#define CLS_SMEM (2*CLS_BUFB + 1024)

// ===== merged prep: weight transpose/convert + embed + bias pack ==========
#define PREP_CONV 3104
__global__ void prep_kernel(const float* __restrict__ Wq,
                            const float* __restrict__ Wk,
                            const float* __restrict__ Wv,
                            const float* __restrict__ Wo,
                            const float* __restrict__ Wc,
                            const float* __restrict__ W1,
                            const float* __restrict__ W2,
                            __half* __restrict__ qkvT,
                            __half* __restrict__ oT,
                            __half* __restrict__ cH,
                            __half* __restrict__ cL,
                            __half* __restrict__ w1T,
                            __half* __restrict__ w2T,
                            const int* __restrict__ ids,
                            const float* __restrict__ emb,
                            const float* __restrict__ bq,
                            const float* __restrict__ bk,
                            const float* __restrict__ bv,
                            float* __restrict__ bqkv,
                            float* __restrict__ X,
                            __half* __restrict__ XH,
                            __half* __restrict__ XL)
{
    const int tb = blockIdx.x;
    const int tx = threadIdx.x, ty = threadIdx.y;

    if (tb >= PREP_CONV) {
        int t = tb - PREP_CONV;
        int d = ty * 32 + tx;
        if (t >= M_TOK) {
            int idx = t - M_TOK;
            int l = idx / 3, seg = idx % 3;
            const float* src = (seg == 0) ? bq : (seg == 1) ? bk : bv;
            bqkv[l * QKV_N + seg * 256 + d] = src[l * 256 + d];
            return;
        }
        int s = t & (S_ - 1);
        int id = ids[t];
        float f = (d < D_ / 2) ? (2.0f * d) : (2.0f * (d - D_ / 2) + 1.0f);
        float inv = exp2f(-f * 13.287712379549449f / (float)D_);
        float v = emb[(size_t)id * D_ + d] + sinf((float)s * inv);
        size_t idx = (size_t)t * D_ + d;
        X[idx] = v;
        __half h = __float2half_rn(v);
        XH[idx] = h;
        XL[idx] = __float2half_rn(v - __half2float(h));
        return;
    }

    __shared__ float t[32][33];
    const float* W;
    __half* H;
    int K, N, Nv, kx, ny;
    bool cls = false;
    if (tb < 768) {
        int mat = tb >> 6, w = tb & 63;
        int src = mat >> 2, l = mat & 3;
        W = ((src == 0) ? Wq : (src == 1) ? Wk : Wv) + (size_t)l * D_ * D_;
        H = qkvT + (size_t)l * QKV_N * D_ + (size_t)src * 256 * D_;
        K = 256; N = 256; Nv = 256; kx = w & 7; ny = w >> 3;
    } else if (tb < 1024) {
        int u = tb - 768; int l = u >> 6, w = u & 63;
        W = Wo + (size_t)l * D_ * D_; H = oT + (size_t)l * D_ * D_;
        K = 256; N = 256; Nv = 256; kx = w & 7; ny = w >> 3;
    } else if (tb < 1056) {
        int u = tb - 1024; kx = u & 7; ny = u >> 3;
        W = Wc; H = cH; K = 256; N = V_; Nv = V_; cls = true;
    } else if (tb < 2080) {
        int u = tb - 1056; int mat = u >> 8, w = u & 255;
        W = W1 + (size_t)mat * D_ * DFF_; H = w1T + (size_t)mat * DFF_ * D_;
        K = 256; N = 1024; Nv = 1024; kx = w & 7; ny = w >> 3;
    } else {
        int u = tb - 2080; int mat = u >> 8, w = u & 255;
        W = W2 + (size_t)mat * DFF_ * D_; H = w2T + (size_t)mat * D_ * DFF_;
        K = 1024; N = 256; Nv = 256; kx = w & 31; ny = w >> 5;
    }
    const int k0 = kx * 32, n0 = ny * 32;
#pragma unroll
    for (int r = 0; r < 4; r++) {
        int n = n0 + tx;
        t[ty + 8 * r][tx] = (n < Nv) ? W[(size_t)(k0 + ty + 8 * r) * N + n] : 0.0f;
    }
    __syncthreads();
    if (!cls) {
#pragma unroll
        for (int r = 0; r < 4; r++)
            H[(size_t)(n0 + ty + 8 * r) * K + k0 + tx] =
                __float2half_rn(t[tx][ty + 8 * r]);
    } else {
#pragma unroll
        for (int r = 0; r < 4; r++) {
            float v = t[tx][ty + 8 * r];
            __half h = __float2half_rn(v);
            size_t o = (size_t)(n0 + ty + 8 * r) * 256 + k0 + tx;
            cH[o] = h;
            cL[o] = __float2half_rn(v - __half2float(h));
        }
    }
}

// ================== HMMA fp16 single-pass GEMM (3-stage) ==================
__device__ __forceinline__ void gemm_fill(
    uint32_t smU, int b, int kb,
    const __half* __restrict__ AHi, const __half* __restrict__ BHi,
    int K, int bm, int bn, int tid)
{
    const int k0 = kb * GKB;
    uint32_t aU = smU + b * BUFB;
    uint32_t bU = aU + APLANE;
#pragma unroll
    for (int i = 0; i < 4; i++) {
        int j   = tid + 256 * i;
        int row = j >> 3;
        int ch  = (j & 7) << 4;
        uint32_t off = swz128((uint32_t)(row * 128 + ch));
        cp_async16(aU + off, (const char*)AHi + ((size_t)(bm + row) * K + k0) * 2 + ch);
    }
#pragma unroll
    for (int i = 0; i < 2; i++) {
        int j   = tid + 256 * i;
        int row = j >> 3;
        int ch  = (j & 7) << 4;
        uint32_t off = swz128((uint32_t)(row * 128 + ch));
        cp_async16(bU + off, (const char*)BHi + ((size_t)(bn + row) * K + k0) * 2 + ch);
    }
}

__global__ __launch_bounds__(256, 3)
void gemm_tc(const __half* __restrict__ AHi,
             const __half* __restrict__ BHi,
             const float* __restrict__ bias,
             float* __restrict__ C,
             __half* __restrict__ CHi,
             int K, int N, int relu, int qcols)
{
    extern __shared__ char dsm_raw[];
    const int tid  = threadIdx.x;
    const int lane = tid & 31;
    const int wid  = tid >> 5;
    const int m0   = (wid >> 1) * 32;
    const int n0   = (wid & 1) * 32;
    const int bm   = blockIdx.y * GBM;
    const int bn   = blockIdx.x * GBN;
    const int nk   = K / GKB;

    uint32_t rawU = smem_u32(dsm_raw);
    uint32_t smU  = (rawU + 1023u) & ~1023u;

    float acc[2][4][4];
#pragma unroll
    for (int mi = 0; mi < 2; mi++)
#pragma unroll
        for (int ni = 0; ni < 4; ni++)
#pragma unroll
            for (int e = 0; e < 4; e++) acc[mi][ni][e] = 0.0f;

    gemm_fill(smU, 0, 0, AHi, BHi, K, bm, bn, tid);
    cp_commit();
    gemm_fill(smU, 1, 1, AHi, BHi, K, bm, bn, tid);
    cp_commit();

    const int a_row = m0 + (lane & 15);
    const int a_kb  = (lane >> 4) * 16;
    const int b_row = n0 + ((lane >> 4) << 3) + (lane & 7);
    const int b_kb  = ((lane >> 3) & 1) * 16;

    int bf = 0;
    for (int kb = 0; kb < nk; kb++) {
        if (kb + 1 < nk) cp_wait1(); else cp_wait0();
        __syncthreads();
        if (kb + 2 < nk) {
            int nb = bf + 2; if (nb >= 3) nb -= 3;
            gemm_fill(smU, nb, kb + 2, AHi, BHi, K, bm, bn, tid);
            cp_commit();
        }

        const uint32_t aU = smU + bf * BUFB;
        const uint32_t bU = aU + APLANE;
#pragma unroll
        for (int ks = 0; ks < 4; ks++) {
            const int kbase = ks * 32;
            uint32_t ah[2][4], bh[2][4];
#pragma unroll
            for (int mi = 0; mi < 2; mi++)
                ldsm_x4(ah[mi], aU + swz128((uint32_t)((a_row + mi * 16) * 128 + kbase + a_kb)));
#pragma unroll
            for (int bi = 0; bi < 2; bi++)
                ldsm_x4(bh[bi], bU + swz128((uint32_t)((b_row + bi * 16) * 128 + kbase + b_kb)));
#pragma unroll
            for (int mi = 0; mi < 2; mi++)
#pragma unroll
                for (int ni = 0; ni < 4; ni++)
                    mma_f16(acc[mi][ni], ah[mi],
                            bh[ni >> 1][(ni & 1) * 2], bh[ni >> 1][(ni & 1) * 2 + 1]);
        }
        if (++bf == 3) bf = 0;
    }

    const int gr = lane >> 2;
    const int gc = (lane & 3) * 2;
#pragma unroll
    for (int mi = 0; mi < 2; mi++) {
        int r0 = bm + m0 + mi * 16 + gr;
#pragma unroll
        for (int ni = 0; ni < 4; ni++) {
            int c = bn + n0 + ni * 8 + gc;
            int c0s = (c < N) ? c : N - 1;
            int c1s = (c + 1 < N) ? c + 1 : N - 1;
            float v00 = acc[mi][ni][0] + bias[c0s];
            float v01 = acc[mi][ni][1] + bias[c1s];
            float v10 = acc[mi][ni][2] + bias[c0s];
            float v11 = acc[mi][ni][3] + bias[c1s];
            if (relu) {
                v00 = fmaxf(v00, 0.f); v01 = fmaxf(v01, 0.f);
                v10 = fmaxf(v10, 0.f); v11 = fmaxf(v11, 0.f);
            }
            if (CHi) {
                if (c < qcols) {
                    v00 *= SCL2E; v01 *= SCL2E; v10 *= SCL2E; v11 *= SCL2E;
                }
                *(uint32_t*)(CHi + (size_t)r0 * N + c) = pack_f2h(v00, v01);
                *(uint32_t*)(CHi + (size_t)(r0 + 8) * N + c) = pack_f2h(v10, v11);
            } else if (c + 1 < N) {
                *(float2*)(C + (size_t)r0 * N + c) = make_float2(v00, v01);
                *(float2*)(C + (size_t)(r0 + 8) * N + c) = make_float2(v10, v11);
            } else if (c < N) {
                C[(size_t)r0 * N + c] = v00;
                C[(size_t)(r0 + 8) * N + c] = v10;
            }
        }
    }
}

// ============= classifier GEMM: 3-pass split precision ====================
__device__ __forceinline__ void cls_fill(
    uint32_t smU, int b, int kb,
    const __half* __restrict__ AHi, const __half* __restrict__ ALo,
    const __half* __restrict__ BHi, const __half* __restrict__ BLo,
    int K, int bm, int bn, int tid)
{
    const int k0 = kb * GKB;
    uint32_t aHiU = smU + b * CLS_BUFB;
    uint32_t aLoU = aHiU + APLANE;
    uint32_t bHiU = aHiU + 2 * APLANE;
    uint32_t bLoU = bHiU + BPLANE;
#pragma unroll
    for (int i = 0; i < 4; i++) {
        int j   = tid + 256 * i;
        int row = j >> 3;
        int ch  = (j & 7) << 4;
        uint32_t off = swz128((uint32_t)(row * 128 + ch));
        size_t srcb = ((size_t)(bm + row) * K + k0) * 2 + ch;
        cp_async16(aHiU + off, (const char*)AHi + srcb);
        cp_async16(aLoU + off, (const char*)ALo + srcb);
    }
#pragma unroll
    for (int i = 0; i < 2; i++) {
        int j   = tid + 256 * i;
        int row = j >> 3;
        int ch  = (j & 7) << 4;
        uint32_t off = swz128((uint32_t)(row * 128 + ch));
        size_t srcb = ((size_t)(bn + row) * K + k0) * 2 + ch;
        cp_async16(bHiU + off, (const char*)BHi + srcb);
        cp_async16(bLoU + off, (const char*)BLo + srcb);
    }
}

__global__ __launch_bounds__(256, 2)
void gemm_cls(const __half* __restrict__ AHi,
              const __half* __restrict__ ALo,
              const __half* __restrict__ BHi,
              const __half* __restrict__ BLo,
              const float* __restrict__ bias,
              float* __restrict__ C,
              int K, int N)
{
    extern __shared__ char dsm_raw[];
    const int tid  = threadIdx.x;
    const int lane = tid & 31;
    const int wid  = tid >> 5;
    const int m0   = (wid >> 1) * 32;
    const int n0   = (wid & 1) * 32;
    const int bm   = blockIdx.y * GBM;
    const int bn   = blockIdx.x * GBN;
    const int nk   = K / GKB;

    uint32_t rawU = smem_u32(dsm_raw);
    uint32_t smU  = (rawU + 1023u) & ~1023u;

    float acc[2][4][4];
#pragma unroll
    for (int mi = 0; mi < 2; mi++)
#pragma unroll
        for (int ni = 0; ni < 4; ni++)
#pragma unroll
            for (int e = 0; e < 4; e++) acc[mi][ni][e] = 0.0f;

    cls_fill(smU, 0, 0, AHi, ALo, BHi, BLo, K, bm, bn, tid);
    cp_commit();

    const int a_row = m0 + (lane & 15);
    const int a_kb  = (lane >> 4) * 16;
    const int b_row = n0 + ((lane >> 4) << 3) + (lane & 7);
    const int b_kb  = ((lane >> 3) & 1) * 16;

    for (int kb = 0; kb < nk; kb++) {
        const int b = kb & 1;
        if (kb + 1 < nk) {
            cls_fill(smU, b ^ 1, kb + 1, AHi, ALo, BHi, BLo, K, bm, bn, tid);
            cp_commit();
            cp_wait1();
        } else {
            cp_wait0();
        }
        __syncthreads();

        const uint32_t aU = smU + b * CLS_BUFB;
        const uint32_t bU = aU + 2 * APLANE;
#pragma unroll
        for (int ks = 0; ks < 4; ks++) {
            const int kbase = ks * 32;
            uint32_t ah[2][4], al[2][4], bh[2][4], bl[2][4];
#pragma unroll
            for (int mi = 0; mi < 2; mi++) {
                uint32_t off = swz128((uint32_t)((a_row + mi * 16) * 128 + kbase + a_kb));
                ldsm_x4(ah[mi], aU + off);
                ldsm_x4(al[mi], aU + APLANE + off);
            }
#pragma unroll
            for (int bi = 0; bi < 2; bi++) {
                uint32_t off = swz128((uint32_t)((b_row + bi * 16) * 128 + kbase + b_kb));
                ldsm_x4(bh[bi], bU + off);
                ldsm_x4(bl[bi], bU + BPLANE + off);
            }
#pragma unroll
            for (int mi = 0; mi < 2; mi++)
#pragma unroll
                for (int ni = 0; ni < 4; ni++) {
                    uint32_t h0 = bh[ni >> 1][(ni & 1) * 2];
                    uint32_t h1 = bh[ni >> 1][(ni & 1) * 2 + 1];
                    uint32_t l0 = bl[ni >> 1][(ni & 1) * 2];
                    uint32_t l1 = bl[ni >> 1][(ni & 1) * 2 + 1];
                    mma_f16(acc[mi][ni], ah[mi], h0, h1);
                    mma_f16(acc[mi][ni], ah[mi], l0, l1);
                    mma_f16(acc[mi][ni], al[mi], h0, h1);
                }
        }
        __syncthreads();
    }

    const int gr = lane >> 2;
    const int gc = (lane & 3) * 2;
#pragma unroll
    for (int mi = 0; mi < 2; mi++) {
        int r0 = bm + m0 + mi * 16 + gr;
#pragma unroll
        for (int ni = 0; ni < 4; ni++) {
            int c = bn + n0 + ni * 8 + gc;
            if (c + 1 < N) {
                *(float2*)(C + (size_t)r0 * N + c) =
                    make_float2(acc[mi][ni][0] + bias[c], acc[mi][ni][1] + bias[c + 1]);
                *(float2*)(C + (size_t)(r0 + 8) * N + c) =
                    make_float2(acc[mi][ni][2] + bias[c], acc[mi][ni][3] + bias[c + 1]);
            } else if (c < N) {
                C[(size_t)r0 * N + c] = acc[mi][ni][0] + bias[c];
                C[(size_t)(r0 + 8) * N + c] = acc[mi][ni][2] + bias[c];
            }
        }
    }
}

// ====== fused GEMM (N=256) + bias + residual + LayerNorm (3-stage) ========
// R12 configuration: BM=64, 512 threads (16 warps: 4m x 4n).
#define LN_BM 64
#define LN_AP 8192
#define LN_BP 32768
#define LN_STAGE (LN_AP + LN_BP)       // 40960
#define LN_SMEM (3*LN_STAGE + 1024)    // 123904

__device__ __forceinline__ void ln_fill(
    uint32_t smU, int b, int kb,
    const __half* __restrict__ AHi, const __half* __restrict__ BHi,
    int K, int bm, int tid)
{
    const int k0 = kb * GKB;
    uint32_t aU = smU + b * LN_STAGE;
    uint32_t bU = aU + LN_AP;
    {
        int row = tid >> 3;
        int ch  = (tid & 7) << 4;
        uint32_t off = swz128((uint32_t)(row * 128 + ch));
        cp_async16(aU + off, (const char*)AHi + ((size_t)(bm + row) * K + k0) * 2 + ch);
    }
#pragma unroll
    for (int i = 0; i < 4; i++) {
        int j   = tid + 512 * i;
        int row = j >> 3;
        int ch  = (j & 7) << 4;
        uint32_t off = swz128((uint32_t)(row * 128 + ch));
        cp_async16(bU + off, (const char*)BHi + ((size_t)row * K + k0) * 2 + ch);
    }
}

__global__ __launch_bounds__(512)
void gemm_ln(const __half* __restrict__ AHi,
             const __half* __restrict__ BHi,
             const float* __restrict__ bias,
             const float* __restrict__ g,
             const float* __restrict__ be,
             float* __restrict__ X,
             __half* __restrict__ XH,
             __half* __restrict__ XL,
             int K)
{
    extern __shared__ char dsm_raw[];
    __shared__ float redS[64][4], redQ[64][4];

    const int tid  = threadIdx.x;
    const int lane = tid & 31;
    const int wid  = tid >> 5;
    const int m0   = (wid >> 2) * 16;
    const int n0   = (wid & 3) * 64;
    const int bm   = blockIdx.x * LN_BM;
    const int nk   = K / GKB;

    uint32_t rawU = smem_u32(dsm_raw);
    uint32_t smU  = (rawU + 1023u) & ~1023u;

    float acc[8][4];
#pragma unroll
    for (int ni = 0; ni < 8; ni++)
#pragma unroll
        for (int e = 0; e < 4; e++) acc[ni][e] = 0.0f;

    ln_fill(smU, 0, 0, AHi, BHi, K, bm, tid);
    cp_commit();
    ln_fill(smU, 1, 1, AHi, BHi, K, bm, tid);
    cp_commit();

    const int a_row = m0 + (lane & 15);
    const int a_kb  = (lane >> 4) * 16;
    const int b_rowL = ((lane >> 4) << 3) + (lane & 7);
    const int b_kb  = ((lane >> 3) & 1) * 16;

    int bf = 0;
    for (int kb = 0; kb < nk; kb++) {
        if (kb + 1 < nk) cp_wait1(); else cp_wait0();
        __syncthreads();
        if (kb + 2 < nk) {
            int nb = bf + 2; if (nb >= 3) nb -= 3;
            ln_fill(smU, nb, kb + 2, AHi, BHi, K, bm, tid);
            cp_commit();
        }

        const uint32_t aU = smU + bf * LN_STAGE;
        const uint32_t bU = aU + LN_AP;
#pragma unroll
        for (int ks = 0; ks < 4; ks++) {
            const int kbase = ks * 32;
            uint32_t ah[4], bh[4][4];
            ldsm_x4(ah, aU + swz128((uint32_t)(a_row * 128 + kbase + a_kb)));
#pragma unroll
            for (int bi = 0; bi < 4; bi++)
                ldsm_x4(bh[bi], bU + swz128((uint32_t)((n0 + bi * 16 + b_rowL) * 128 + kbase + b_kb)));
#pragma unroll
            for (int ni = 0; ni < 8; ni++)
                mma_f16(acc[ni], ah,
                        bh[ni >> 1][(ni & 1) * 2], bh[ni >> 1][(ni & 1) * 2 + 1]);
        }
        if (++bf == 3) bf = 0;
    }

    // ---- epilogue: bias + residual, row stats, LN, write ----
    const int gr = lane >> 2;
    const int tg = lane & 3;
    const int nw = wid & 3;

    int rl0 = m0 + gr;
    int rl1 = rl0 + 8;
    size_t gb0 = (size_t)(bm + rl0) * D_;
    size_t gb1 = (size_t)(bm + rl1) * D_;
    {
        float s0 = 0.f, q0 = 0.f, s1 = 0.f, q1 = 0.f;
#pragma unroll
        for (int ni = 0; ni < 8; ni++) {
            int c = n0 + ni * 8 + tg * 2;
            float2 bv = *(const float2*)(bias + c);
            float2 x0 = *(const float2*)(X + gb0 + c);
            float2 x1 = *(const float2*)(X + gb1 + c);
            acc[ni][0] += bv.x + x0.x;
            acc[ni][1] += bv.y + x0.y;
            acc[ni][2] += bv.x + x1.x;
            acc[ni][3] += bv.y + x1.y;
            s0 += acc[ni][0] + acc[ni][1];
            q0 += acc[ni][0] * acc[ni][0] + acc[ni][1] * acc[ni][1];
            s1 += acc[ni][2] + acc[ni][3];
            q1 += acc[ni][2] * acc[ni][2] + acc[ni][3] * acc[ni][3];
        }
#pragma unroll
        for (int o = 1; o <= 2; o <<= 1) {
            s0 += __shfl_xor_sync(0xFFFFFFFFu, s0, o);
            q0 += __shfl_xor_sync(0xFFFFFFFFu, q0, o);
            s1 += __shfl_xor_sync(0xFFFFFFFFu, s1, o);
            q1 += __shfl_xor_sync(0xFFFFFFFFu, q1, o);
        }
        if (tg == 0) {
            redS[rl0][nw] = s0; redQ[rl0][nw] = q0;
            redS[rl1][nw] = s1; redQ[rl1][nw] = q1;
        }
    }
    __syncthreads();

    {
        float S0 = redS[rl0][0] + redS[rl0][1] + redS[rl0][2] + redS[rl0][3];
        float Q0 = redQ[rl0][0] + redQ[rl0][1] + redQ[rl0][2] + redQ[rl0][3];
        float S1 = redS[rl1][0] + redS[rl1][1] + redS[rl1][2] + redS[rl1][3];
        float Q1 = redQ[rl1][0] + redQ[rl1][1] + redQ[rl1][2] + redQ[rl1][3];
        float mean0 = S0 * (1.0f / D_);
        float mean1 = S1 * (1.0f / D_);
        float r0 = rsqrtf(Q0 * (1.0f / D_) - mean0 * mean0 + 1e-5f);
        float r1 = rsqrtf(Q1 * (1.0f / D_) - mean1 * mean1 + 1e-5f);
#pragma unroll
        for (int ni = 0; ni < 8; ni++) {
            int c = n0 + ni * 8 + tg * 2;
            float2 gv = *(const float2*)(g + c);
            float2 bev = *(const float2*)(be + c);
            float o00 = (acc[ni][0] - mean0) * r0 * gv.x + bev.x;
            float o01 = (acc[ni][1] - mean0) * r0 * gv.y + bev.y;
            float o10 = (acc[ni][2] - mean1) * r1 * gv.x + bev.x;
            float o11 = (acc[ni][3] - mean1) * r1 * gv.y + bev.y;
            *(float2*)(X + gb0 + c) = make_float2(o00, o01);
            *(float2*)(X + gb1 + c) = make_float2(o10, o11);
            uint32_t hp, lp;
            split2h(o00, o01, hp, lp);
            *(uint32_t*)(XH + gb0 + c) = hp;
            *(uint32_t*)(XL + gb0 + c) = lp;
            split2h(o10, o11, hp, lp);
            *(uint32_t*)(XH + gb1 + c) = hp;
            *(uint32_t*)(XL + gb1 + c) = lp;
        }
    }
}

// ========== tensor-core causal flash attention (no-max softmax) ===========
// 128 queries per CTA, 256 threads (8 warps x 16 rows). Warps above their
// causal diagonal skip compute for that tile (fills/barriers still uniform).
#define AT_PITCH 80
#define AT_Q 0
#define AT_KV 10240
#define AT_BUF 10240
#define AT_SMEM (AT_KV + 3*AT_BUF + 1024)   // 41984

__device__ __forceinline__ void attn_fill_kv(
    uint32_t smU, int buf,
    const __half* __restrict__ Ph,
    size_t rowbase, int kt, int h, int tid)
{
    uint32_t base = smU + AT_KV + buf * AT_BUF;
    int row = tid >> 2, ch = (tid & 3) * 16;     // 256 threads cover 64 rows x 4 chunks
    size_t gk = ((rowbase + kt + row) * QKV_N + 256 + h * DH_) * 2 + ch;
    size_t gv = gk + 512;
    uint32_t d = row * AT_PITCH + ch;
    cp_async16(base + d,        (const char*)Ph + gk);
    cp_async16(base + 5120 + d, (const char*)Ph + gv);
}

__global__ __launch_bounds__(256)
void attn_tc(const __half* __restrict__ Ph,
             __half* __restrict__ YH,
             const int* __restrict__ tsl)
{
    extern __shared__ char asmem_raw[];
    const int tid = threadIdx.x, lane = tid & 31, w = tid >> 5;
    const int qblk = (gridDim.x - 1) - blockIdx.x;   // longest-first
    const int h = blockIdx.y, b = blockIdx.z;
    const int q0 = qblk * 128;
    const int len = tsl[b];
    const int gr = lane >> 2, tg = lane & 3;
    uint32_t rawU = smem_u32(asmem_raw);
    const uint32_t smU = (rawU + 1023u) & ~1023u;
    const size_t rowbase = (size_t)b * S_;
    const int nt = 2 * qblk + 2;

    // stage Q (128 rows x 64B = 512 chunks over 256 threads)
#pragma unroll
    for (int i = 0; i < 2; i++) {
        int jj = tid + 256 * i;
        int row = jj >> 2, ch = (jj & 3) * 16;
        size_t src = ((rowbase + q0 + row) * QKV_N + h * DH_) * 2 + ch;
        cp_async16(smU + AT_Q + row * AT_PITCH + ch, (const char*)Ph + src);
    }
    attn_fill_kv(smU, 0, Ph, rowbase, 0, h, tid);
    cp_commit();
    attn_fill_kv(smU, 1, Ph, rowbase, 64, h, tid);
    cp_commit();
    cp_wait1();
    __syncthreads();

    uint32_t qf[2][4];
    {
        int r8 = (lane & 7) + ((lane >> 3) & 1) * 8;
        int cb = ((lane >> 4) & 1) * 16;
#pragma unroll
        for (int kk = 0; kk < 2; kk++)
            ldsm_x4(qf[kk], smU + AT_Q + (uint32_t)(w * 16 + r8) * AT_PITCH + kk * 32 + cb);
    }

    float o[4][4];
    float lrow[2] = {0.f, 0.f};
#pragma unroll
    for (int nd = 0; nd < 4; nd++)
#pragma unroll
        for (int e = 0; e < 4; e++) o[nd][e] = 0.f;

    const int qw0 = q0 + w * 16;
    const int qwmax = qw0 + 15;
    const int l7 = lane & 7;
    const int khb = ((lane >> 3) & 1) * 16;
    const int nsel = (lane >> 4) & 1;
    const int l15 = lane & 15;

    int bf = 0;
    for (int t = 0; t < nt; t++) {
        const int kt = t * 64;
        if (t + 1 < nt) cp_wait1(); else cp_wait0();
        __syncthreads();
        if (t + 2 < nt) {
            int nb = bf + 2; if (nb >= 3) nb -= 3;
            attn_fill_kv(smU, nb, Ph, rowbase, kt + 128, h, tid);
            cp_commit();
        }

        if (kt <= qwmax) {   // skip tiles fully above this warp's diagonal
            const uint32_t kb = smU + AT_KV + bf * AT_BUF;
            const uint32_t vb = kb + 5120;

            float s[8][4];
#pragma unroll
            for (int ni = 0; ni < 8; ni++)
#pragma unroll
                for (int e = 0; e < 4; e++) s[ni][e] = 0.f;
#pragma unroll
            for (int kk = 0; kk < 2; kk++)
#pragma unroll
                for (int ni = 0; ni < 8; ni += 2) {
                    uint32_t kf[4];
                    ldsm_x4(kf, kb + (uint32_t)((ni + nsel) * 8 + l7) * AT_PITCH + kk * 32 + khb);
                    mma_f16(s[ni],     qf[kk], kf[0], kf[1]);
                    mma_f16(s[ni + 1], qf[kk], kf[2], kf[3]);
                }

            if (kt + 63 > qw0 || kt + 64 > len) {
                int r0 = qw0 + gr, r1 = r0 + 8;
#pragma unroll
                for (int ni = 0; ni < 8; ni++) {
                    int c0 = kt + ni * 8 + tg * 2, c1 = c0 + 1;
                    if (c0 > r0 || c0 >= len) s[ni][0] = -1e30f;
                    if (c1 > r0 || c1 >= len) s[ni][1] = -1e30f;
                    if (c0 > r1 || c0 >= len) s[ni][2] = -1e30f;
                    if (c1 > r1 || c1 >= len) s[ni][3] = -1e30f;
                }
            }

#pragma unroll
            for (int ni = 0; ni < 8; ni++) {
                float p0 = exp2f(s[ni][0]);
                float p1 = exp2f(s[ni][1]);
                float p2 = exp2f(s[ni][2]);
                float p3 = exp2f(s[ni][3]);
                s[ni][0] = p0; s[ni][1] = p1; s[ni][2] = p2; s[ni][3] = p3;
                lrow[0] += p0 + p1;
                lrow[1] += p2 + p3;
            }

#pragma unroll
            for (int j = 0; j < 4; j++) {
                uint32_t pa[4];
                pa[0] = pack_f2h(s[2*j][0],   s[2*j][1]);
                pa[1] = pack_f2h(s[2*j][2],   s[2*j][3]);
                pa[2] = pack_f2h(s[2*j+1][0], s[2*j+1][1]);
                pa[3] = pack_f2h(s[2*j+1][2], s[2*j+1][3]);
#pragma unroll
                for (int nd = 0; nd < 4; nd += 2) {
                    uint32_t vf[4];
                    ldsm_x4t(vf, vb + (uint32_t)(16 * j + l15) * AT_PITCH + (nd + nsel) * 16);
                    mma_f16(o[nd],     pa, vf[0], vf[1]);
                    mma_f16(o[nd + 1], pa, vf[2], vf[3]);
                }
            }
        }
        if (++bf == 3) bf = 0;
    }

#pragma unroll
    for (int hh = 0; hh < 2; hh++) {
        float v = lrow[hh];
        v += __shfl_xor_sync(0xFFFFFFFFu, v, 1);
        v += __shfl_xor_sync(0xFFFFFFFFu, v, 2);
        lrow[hh] = v;
    }
    int r0 = qw0 + gr, r1 = r0 + 8;
    float inv0 = (r0 < len && lrow[0] > 0.f) ? 1.0f / lrow[0] : 0.f;
    float inv1 = (r1 < len && lrow[1] > 0.f) ? 1.0f / lrow[1] : 0.f;
#pragma unroll
    for (int nd = 0; nd < 4; nd++) {
        int col = h * DH_ + nd * 8 + tg * 2;
        *(uint32_t*)(YH + (rowbase + r0) * D_ + col) = pack_f2h(o[nd][0] * inv0, o[nd][1] * inv0);
        *(uint32_t*)(YH + (rowbase + r1) * D_ + col) = pack_f2h(o[nd][2] * inv1, o[nd][3] * inv1);
    }
}

// =========================== launcher ====================================
extern "C" void kernel_launch(void* const* d_in, const int* in_sizes, int n_in,
                              void* d_out, int out_size)
{
    const int*   ids = (const int*)  d_in[0];
    const int*   tsl = (const int*)  d_in[1];
    const float* emb = (const float*)d_in[2];
    const float* Wq  = (const float*)d_in[3];
    const float* bq  = (const float*)d_in[4];
    const float* Wk  = (const float*)d_in[5];
    const float* bk  = (const float*)d_in[6];
    const float* Wv  = (const float*)d_in[7];
    const float* bv  = (const float*)d_in[8];
    const float* Wo  = (const float*)d_in[9];
    const float* bo  = (const float*)d_in[10];
    const float* W1  = (const float*)d_in[11];
    const float* b1  = (const float*)d_in[12];
    const float* W2  = (const float*)d_in[13];
    const float* b2  = (const float*)d_in[14];
    const float* g1  = (const float*)d_in[15];
    const float* be1 = (const float*)d_in[16];
    const float* g2  = (const float*)d_in[17];
    const float* be2 = (const float*)d_in[18];
    const float* Wc  = (const float*)d_in[19];
    const float* bc  = (const float*)d_in[20];
    float* out = (float*)d_out;

    float *x, *bqkv;
    cudaGetSymbolAddress((void**)&x,   g_x);
    cudaGetSymbolAddress((void**)&bqkv, g_bqkv);

    __half *xh, *xl, *yh, *ffh, *qkvh;
    cudaGetSymbolAddress((void**)&xh,  g_xh);
    cudaGetSymbolAddress((void**)&xl,  g_xl);
    cudaGetSymbolAddress((void**)&yh,  g_yh);
    cudaGetSymbolAddress((void**)&ffh, g_ffh);
    cudaGetSymbolAddress((void**)&qkvh, g_qkvh);

    __half *qkvT, *oT, *w1T, *w2T, *wch, *wcl;
    cudaGetSymbolAddress((void**)&qkvT, g_qkvT);
    cudaGetSymbolAddress((void**)&oT,   g_oT);
    cudaGetSymbolAddress((void**)&w1T,  g_1T);
    cudaGetSymbolAddress((void**)&w2T,  g_2T);
    cudaGetSymbolAddress((void**)&wch,  g_cT_hi);
    cudaGetSymbolAddress((void**)&wcl,  g_cT_lo);

    cudaFuncSetAttribute((const void*)gemm_tc,
                         cudaFuncAttributeMaxDynamicSharedMemorySize, GEMM_SMEM);
    cudaFuncSetAttribute((const void*)gemm_cls,
                         cudaFuncAttributeMaxDynamicSharedMemorySize, CLS_SMEM);
    cudaFuncSetAttribute((const void*)gemm_ln,
                         cudaFuncAttributeMaxDynamicSharedMemorySize, LN_SMEM);
    cudaFuncSetAttribute((const void*)attn_tc,
                         cudaFuncAttributeMaxDynamicSharedMemorySize, AT_SMEM);

    prep_kernel<<<PREP_CONV + M_TOK + 3 * L_, dim3(32, 8)>>>(
        Wq, Wk, Wv, Wo, Wc, W1, W2, qkvT, oT, wch, wcl, w1T, w2T,
        ids, emb, bq, bk, bv, bqkv, x, xh, xl);

    dim3 gQKV(QKV_N / GBN, M_TOK / GBM);
    dim3 gF  (DFF_ / GBN,  M_TOK / GBM);
    dim3 gC  (2,           M_TOK / GBM);
    const int gLN = M_TOK / LN_BM;   // 128

    for (int l = 0; l < L_; l++) {
        size_t qoff  = (size_t)l * QKV_N * D_;
        size_t ooff  = (size_t)l * D_ * D_;
        size_t w1off = (size_t)l * DFF_ * D_;

        gemm_tc<<<gQKV, 256, GEMM_SMEM>>>(xh, qkvT + qoff,
                                          bqkv + l * QKV_N, 0, qkvh, D_, QKV_N, 0, 256);
        attn_tc<<<dim3(S_ / 128, H_, B_), 256, AT_SMEM>>>(qkvh, yh, tsl);

        gemm_ln<<<gLN, 512, LN_SMEM>>>(yh, oT + ooff,
                                       bo + l * D_, g1 + l * D_, be1 + l * D_,
                                       x, xh, xl, D_);

        gemm_tc<<<gF, 256, GEMM_SMEM>>>(xh, w1T + w1off,
                                        b1 + l * DFF_, 0, ffh, D_, DFF_, 1, 0);

        gemm_ln<<<gLN, 512, LN_SMEM>>>(ffh, w2T + w1off,
                                       b2 + l * D_, g2 + l * D_, be2 + l * D_,
                                       x, xh, xl, DFF_);
    }

    gemm_cls<<<gC, 256, CLS_SMEM>>>(xh, xl, wch, wcl, bc, out, D_, V_);
}

// round 15
// speedup vs baseline: 1.0382x; 1.0382x over previous
#include <cuda_runtime.h>
#include <cuda_fp16.h>
#include <math.h>
#include <stdint.h>

// Problem constants
#define B_  8
#define S_  1024
#define D_  256
#define H_  8
#define DH_ 32
#define L_  4
#define V_  100
#define DFF_ 1024
#define M_TOK (B_ * S_)   // 8192
#define QKV_N 768

#define SCL2E 0.2550348243f   // log2(e)/sqrt(32)

// -------- scratch (static device globals; no runtime allocation) --------
__device__ __half g_xh  [M_TOK * D_],  g_xl[M_TOK * D_];
__device__ __half g_yh  [M_TOK * D_];
__device__ __half g_ffh [M_TOK * DFF_];
__device__ __half g_qkvh[M_TOK * QKV_N];

__device__ __half g_qkvT[L_*QKV_N*D_];
__device__ __half g_oT  [L_*D_*D_];
__device__ __half g_1T  [L_*DFF_*D_];
__device__ __half g_2T  [L_*D_*DFF_];
__device__ __half g_cT_hi[128*D_], g_cT_lo[128*D_];
__device__ float g_bqkv[L_ * QKV_N];

// =========================== PTX helpers ==================================
__device__ __forceinline__ uint32_t smem_u32(const void* p) {
    uint32_t r;
    asm("{ .reg .u64 t; cvta.to.shared.u64 t, %1; cvt.u32.u64 %0, t; }"
        : "=r"(r) : "l"(p));
    return r;
}
__device__ __forceinline__ void cp_async16(uint32_t dst, const void* src) {
    asm volatile("cp.async.cg.shared.global [%0], [%1], 16;"
                 :: "r"(dst), "l"(src));
}
__device__ __forceinline__ void cp_commit() {
    asm volatile("cp.async.commit_group;" ::: "memory");
}
__device__ __forceinline__ void cp_wait1() {
    asm volatile("cp.async.wait_group 1;" ::: "memory");
}
__device__ __forceinline__ void cp_wait0() {
    asm volatile("cp.async.wait_group 0;" ::: "memory");
}
__device__ __forceinline__ void ldsm_x4(uint32_t* r, uint32_t addr) {
    asm volatile("ldmatrix.sync.aligned.m8n8.x4.shared.b16 {%0,%1,%2,%3}, [%4];"
                 : "=r"(r[0]), "=r"(r[1]), "=r"(r[2]), "=r"(r[3]) : "r"(addr));
}
__device__ __forceinline__ void ldsm_x2(uint32_t* r, uint32_t addr) {
    asm volatile("ldmatrix.sync.aligned.m8n8.x2.shared.b16 {%0,%1}, [%2];"
                 : "=r"(r[0]), "=r"(r[1]) : "r"(addr));
}
__device__ __forceinline__ void ldsm_x4t(uint32_t* r, uint32_t addr) {
    asm volatile("ldmatrix.sync.aligned.m8n8.x4.trans.shared.b16 {%0,%1,%2,%3}, [%4];"
                 : "=r"(r[0]), "=r"(r[1]), "=r"(r[2]), "=r"(r[3]) : "r"(addr));
}
__device__ __forceinline__ void mma_f16(float* d, const uint32_t* a,
                                        uint32_t b0, uint32_t b1) {
    asm volatile(
        "mma.sync.aligned.m16n8k16.row.col.f32.f16.f16.f32 "
        "{%0,%1,%2,%3}, {%4,%5,%6,%7}, {%8,%9}, {%0,%1,%2,%3};"
        : "+f"(d[0]), "+f"(d[1]), "+f"(d[2]), "+f"(d[3])
        : "r"(a[0]), "r"(a[1]), "r"(a[2]), "r"(a[3]), "r"(b0), "r"(b1));
}
__device__ __forceinline__ uint32_t swz128(uint32_t x) {
    return x ^ ((x >> 3) & 0x70u);
}
__device__ __forceinline__ uint32_t pack_h2(__half a, __half b) {
    __half2 t(a, b);
    return *reinterpret_cast<uint32_t*>(&t);
}
__device__ __forceinline__ uint32_t pack_f2h(float a, float b) {
    __half2 t = __floats2half2_rn(a, b);
    return *reinterpret_cast<uint32_t*>(&t);
}
__device__ __forceinline__ void split2h(float a, float b, uint32_t& hi, uint32_t& lo) {
    __half h0 = __float2half_rn(a);
    __half h1 = __float2half_rn(b);
    __half l0 = __float2half_rn(a - __half2float(h0));
    __half l1 = __float2half_rn(b - __half2float(h1));
    hi = pack_h2(h0, h1);
    lo = pack_h2(l0, l1);
}
__device__ __forceinline__ float2 h2f2(uint32_t u) {
    __half2 t = *reinterpret_cast<__half2*>(&u);
    return __half22float2(t);
}

// ===================== GEMM tiling constants ==============================
#define GBM 128
#define GBN 64
#define GKB 64
#define APLANE 16384
#define BPLANE 8192
#define BUFB (APLANE + BPLANE)
#define GEMM_SMEM (3*BUFB + 1024)
#define CLS_BUFB (2*APLANE + 2*BPLANE)
#define CLS_SMEM (2*CLS_BUFB + 1024)

// ===== merged prep: weight transpose/convert + embed + bias pack ==========
#define PREP_CONV 3104
__global__ void prep_kernel(const float* __restrict__ Wq,
                            const float* __restrict__ Wk,
                            const float* __restrict__ Wv,
                            const float* __restrict__ Wo,
                            const float* __restrict__ Wc,
                            const float* __restrict__ W1,
                            const float* __restrict__ W2,
                            __half* __restrict__ qkvT,
                            __half* __restrict__ oT,
                            __half* __restrict__ cH,
                            __half* __restrict__ cL,
                            __half* __restrict__ w1T,
                            __half* __restrict__ w2T,
                            const int* __restrict__ ids,
                            const float* __restrict__ emb,
                            const float* __restrict__ bq,
                            const float* __restrict__ bk,
                            const float* __restrict__ bv,
                            float* __restrict__ bqkv,
                            __half* __restrict__ XH,
                            __half* __restrict__ XL)
{
    const int tb = blockIdx.x;
    const int tx = threadIdx.x, ty = threadIdx.y;

    if (tb >= PREP_CONV) {
        int t = tb - PREP_CONV;
        int d = ty * 32 + tx;
        if (t >= M_TOK) {
            int idx = t - M_TOK;
            int l = idx / 3, seg = idx % 3;
            const float* src = (seg == 0) ? bq : (seg == 1) ? bk : bv;
            bqkv[l * QKV_N + seg * 256 + d] = src[l * 256 + d];
            return;
        }
        int s = t & (S_ - 1);
        int id = ids[t];
        float f = (d < D_ / 2) ? (2.0f * d) : (2.0f * (d - D_ / 2) + 1.0f);
        float inv = exp2f(-f * 13.287712379549449f / (float)D_);
        float v = emb[(size_t)id * D_ + d] + sinf((float)s * inv);
        size_t idx = (size_t)t * D_ + d;
        __half h = __float2half_rn(v);
        XH[idx] = h;
        XL[idx] = __float2half_rn(v - __half2float(h));
        return;
    }

    __shared__ float t[32][33];
    const float* W;
    __half* H;
    int K, N, Nv, kx, ny;
    bool cls = false;
    if (tb < 768) {
        int mat = tb >> 6, w = tb & 63;
        int src = mat >> 2, l = mat & 3;
        W = ((src == 0) ? Wq : (src == 1) ? Wk : Wv) + (size_t)l * D_ * D_;
        H = qkvT + (size_t)l * QKV_N * D_ + (size_t)src * 256 * D_;
        K = 256; N = 256; Nv = 256; kx = w & 7; ny = w >> 3;
    } else if (tb < 1024) {
        int u = tb - 768; int l = u >> 6, w = u & 63;
        W = Wo + (size_t)l * D_ * D_; H = oT + (size_t)l * D_ * D_;
        K = 256; N = 256; Nv = 256; kx = w & 7; ny = w >> 3;
    } else if (tb < 1056) {
        int u = tb - 1024; kx = u & 7; ny = u >> 3;
        W = Wc; H = cH; K = 256; N = V_; Nv = V_; cls = true;
    } else if (tb < 2080) {
        int u = tb - 1056; int mat = u >> 8, w = u & 255;
        W = W1 + (size_t)mat * D_ * DFF_; H = w1T + (size_t)mat * DFF_ * D_;
        K = 256; N = 1024; Nv = 1024; kx = w & 7; ny = w >> 3;
    } else {
        int u = tb - 2080; int mat = u >> 8, w = u & 255;
        W = W2 + (size_t)mat * DFF_ * D_; H = w2T + (size_t)mat * D_ * DFF_;
        K = 1024; N = 256; Nv = 256; kx = w & 31; ny = w >> 5;
    }
    const int k0 = kx * 32, n0 = ny * 32;
#pragma unroll
    for (int r = 0; r < 4; r++) {
        int n = n0 + tx;
        t[ty + 8 * r][tx] = (n < Nv) ? W[(size_t)(k0 + ty + 8 * r) * N + n] : 0.0f;
    }
    __syncthreads();
    if (!cls) {
#pragma unroll
        for (int r = 0; r < 4; r++)
            H[(size_t)(n0 + ty + 8 * r) * K + k0 + tx] =
                __float2half_rn(t[tx][ty + 8 * r]);
    } else {
#pragma unroll
        for (int r = 0; r < 4; r++) {
            float v = t[tx][ty + 8 * r];
            __half h = __float2half_rn(v);
            size_t o = (size_t)(n0 + ty + 8 * r) * 256 + k0 + tx;
            cH[o] = h;
            cL[o] = __float2half_rn(v - __half2float(h));
        }
    }
}

// ================== HMMA fp16 single-pass GEMM (3-stage) ==================
__device__ __forceinline__ void gemm_fill(
    uint32_t smU, int b, int kb,
    const __half* __restrict__ AHi, const __half* __restrict__ BHi,
    int K, int bm, int bn, int tid)
{
    const int k0 = kb * GKB;
    uint32_t aU = smU + b * BUFB;
    uint32_t bU = aU + APLANE;
#pragma unroll
    for (int i = 0; i < 4; i++) {
        int j   = tid + 256 * i;
        int row = j >> 3;
        int ch  = (j & 7) << 4;
        uint32_t off = swz128((uint32_t)(row * 128 + ch));
        cp_async16(aU + off, (const char*)AHi + ((size_t)(bm + row) * K + k0) * 2 + ch);
    }
#pragma unroll
    for (int i = 0; i < 2; i++) {
        int j   = tid + 256 * i;
        int row = j >> 3;
        int ch  = (j & 7) << 4;
        uint32_t off = swz128((uint32_t)(row * 128 + ch));
        cp_async16(bU + off, (const char*)BHi + ((size_t)(bn + row) * K + k0) * 2 + ch);
    }
}

__global__ __launch_bounds__(256, 3)
void gemm_tc(const __half* __restrict__ AHi,
             const __half* __restrict__ BHi,
             const float* __restrict__ bias,
             float* __restrict__ C,
             __half* __restrict__ CHi,
             int K, int N, int relu, int qcols)
{
    extern __shared__ char dsm_raw[];
    const int tid  = threadIdx.x;
    const int lane = tid & 31;
    const int wid  = tid >> 5;
    const int m0   = (wid >> 1) * 32;
    const int n0   = (wid & 1) * 32;
    const int bm   = blockIdx.y * GBM;
    const int bn   = blockIdx.x * GBN;
    const int nk   = K / GKB;

    uint32_t rawU = smem_u32(dsm_raw);
    uint32_t smU  = (rawU + 1023u) & ~1023u;

    float acc[2][4][4];
#pragma unroll
    for (int mi = 0; mi < 2; mi++)
#pragma unroll
        for (int ni = 0; ni < 4; ni++)
#pragma unroll
            for (int e = 0; e < 4; e++) acc[mi][ni][e] = 0.0f;

    gemm_fill(smU, 0, 0, AHi, BHi, K, bm, bn, tid);
    cp_commit();
    gemm_fill(smU, 1, 1, AHi, BHi, K, bm, bn, tid);
    cp_commit();

    const int a_row = m0 + (lane & 15);
    const int a_kb  = (lane >> 4) * 16;
    const int b_row = n0 + ((lane >> 4) << 3) + (lane & 7);
    const int b_kb  = ((lane >> 3) & 1) * 16;

    int bf = 0;
    for (int kb = 0; kb < nk; kb++) {
        if (kb + 1 < nk) cp_wait1(); else cp_wait0();
        __syncthreads();
        if (kb + 2 < nk) {
            int nb = bf + 2; if (nb >= 3) nb -= 3;
            gemm_fill(smU, nb, kb + 2, AHi, BHi, K, bm, bn, tid);
            cp_commit();
        }

        const uint32_t aU = smU + bf * BUFB;
        const uint32_t bU = aU + APLANE;
#pragma unroll
        for (int ks = 0; ks < 4; ks++) {
            const int kbase = ks * 32;
            uint32_t ah[2][4], bh[2][4];
#pragma unroll
            for (int mi = 0; mi < 2; mi++)
                ldsm_x4(ah[mi], aU + swz128((uint32_t)((a_row + mi * 16) * 128 + kbase + a_kb)));
#pragma unroll
            for (int bi = 0; bi < 2; bi++)
                ldsm_x4(bh[bi], bU + swz128((uint32_t)((b_row + bi * 16) * 128 + kbase + b_kb)));
#pragma unroll
            for (int mi = 0; mi < 2; mi++)
#pragma unroll
                for (int ni = 0; ni < 4; ni++)
                    mma_f16(acc[mi][ni], ah[mi],
                            bh[ni >> 1][(ni & 1) * 2], bh[ni >> 1][(ni & 1) * 2 + 1]);
        }
        if (++bf == 3) bf = 0;
    }

    const int gr = lane >> 2;
    const int gc = (lane & 3) * 2;
#pragma unroll
    for (int mi = 0; mi < 2; mi++) {
        int r0 = bm + m0 + mi * 16 + gr;
#pragma unroll
        for (int ni = 0; ni < 4; ni++) {
            int c = bn + n0 + ni * 8 + gc;
            int c0s = (c < N) ? c : N - 1;
            int c1s = (c + 1 < N) ? c + 1 : N - 1;
            float v00 = acc[mi][ni][0] + bias[c0s];
            float v01 = acc[mi][ni][1] + bias[c1s];
            float v10 = acc[mi][ni][2] + bias[c0s];
            float v11 = acc[mi][ni][3] + bias[c1s];
            if (relu) {
                v00 = fmaxf(v00, 0.f); v01 = fmaxf(v01, 0.f);
                v10 = fmaxf(v10, 0.f); v11 = fmaxf(v11, 0.f);
            }
            if (CHi) {
                if (c < qcols) {
                    v00 *= SCL2E; v01 *= SCL2E; v10 *= SCL2E; v11 *= SCL2E;
                }
                *(uint32_t*)(CHi + (size_t)r0 * N + c) = pack_f2h(v00, v01);
                *(uint32_t*)(CHi + (size_t)(r0 + 8) * N + c) = pack_f2h(v10, v11);
            } else if (c + 1 < N) {
                *(float2*)(C + (size_t)r0 * N + c) = make_float2(v00, v01);
                *(float2*)(C + (size_t)(r0 + 8) * N + c) = make_float2(v10, v11);
            } else if (c < N) {
                C[(size_t)r0 * N + c] = v00;
                C[(size_t)(r0 + 8) * N + c] = v10;
            }
        }
    }
}

// ============= classifier GEMM: 3-pass split precision ====================
__device__ __forceinline__ void cls_fill(
    uint32_t smU, int b, int kb,
    const __half* __restrict__ AHi, const __half* __restrict__ ALo,
    const __half* __restrict__ BHi, const __half* __restrict__ BLo,
    int K, int bm, int bn, int tid)
{
    const int k0 = kb * GKB;
    uint32_t aHiU = smU + b * CLS_BUFB;
    uint32_t aLoU = aHiU + APLANE;
    uint32_t bHiU = aHiU + 2 * APLANE;
    uint32_t bLoU = bHiU + BPLANE;
#pragma unroll
    for (int i = 0; i < 4; i++) {
        int j   = tid + 256 * i;
        int row = j >> 3;
        int ch  = (j & 7) << 4;
        uint32_t off = swz128((uint32_t)(row * 128 + ch));
        size_t srcb = ((size_t)(bm + row) * K + k0) * 2 + ch;
        cp_async16(aHiU + off, (const char*)AHi + srcb);
        cp_async16(aLoU + off, (const char*)ALo + srcb);
    }
#pragma unroll
    for (int i = 0; i < 2; i++) {
        int j   = tid + 256 * i;
        int row = j >> 3;
        int ch  = (j & 7) << 4;
        uint32_t off = swz128((uint32_t)(row * 128 + ch));
        size_t srcb = ((size_t)(bn + row) * K + k0) * 2 + ch;
        cp_async16(bHiU + off, (const char*)BHi + srcb);
        cp_async16(bLoU + off, (const char*)BLo + srcb);
    }
}

__global__ __launch_bounds__(256, 2)
void gemm_cls(const __half* __restrict__ AHi,
              const __half* __restrict__ ALo,
              const __half* __restrict__ BHi,
              const __half* __restrict__ BLo,
              const float* __restrict__ bias,
              float* __restrict__ C,
              int K, int N)
{
    extern __shared__ char dsm_raw[];
    const int tid  = threadIdx.x;
    const int lane = tid & 31;
    const int wid  = tid >> 5;
    const int m0   = (wid >> 1) * 32;
    const int n0   = (wid & 1) * 32;
    const int bm   = blockIdx.y * GBM;
    const int bn   = blockIdx.x * GBN;
    const int nk   = K / GKB;

    uint32_t rawU = smem_u32(dsm_raw);
    uint32_t smU  = (rawU + 1023u) & ~1023u;

    float acc[2][4][4];
#pragma unroll
    for (int mi = 0; mi < 2; mi++)
#pragma unroll
        for (int ni = 0; ni < 4; ni++)
#pragma unroll
            for (int e = 0; e < 4; e++) acc[mi][ni][e] = 0.0f;

    cls_fill(smU, 0, 0, AHi, ALo, BHi, BLo, K, bm, bn, tid);
    cp_commit();

    const int a_row = m0 + (lane & 15);
    const int a_kb  = (lane >> 4) * 16;
    const int b_row = n0 + ((lane >> 4) << 3) + (lane & 7);
    const int b_kb  = ((lane >> 3) & 1) * 16;

    for (int kb = 0; kb < nk; kb++) {
        const int b = kb & 1;
        if (kb + 1 < nk) {
            cls_fill(smU, b ^ 1, kb + 1, AHi, ALo, BHi, BLo, K, bm, bn, tid);
            cp_commit();
            cp_wait1();
        } else {
            cp_wait0();
        }
        __syncthreads();

        const uint32_t aU = smU + b * CLS_BUFB;
        const uint32_t bU = aU + 2 * APLANE;
#pragma unroll
        for (int ks = 0; ks < 4; ks++) {
            const int kbase = ks * 32;
            uint32_t ah[2][4], al[2][4], bh[2][4], bl[2][4];
#pragma unroll
            for (int mi = 0; mi < 2; mi++) {
                uint32_t off = swz128((uint32_t)((a_row + mi * 16) * 128 + kbase + a_kb));
                ldsm_x4(ah[mi], aU + off);
                ldsm_x4(al[mi], aU + APLANE + off);
            }
#pragma unroll
            for (int bi = 0; bi < 2; bi++) {
                uint32_t off = swz128((uint32_t)((b_row + bi * 16) * 128 + kbase + b_kb));
                ldsm_x4(bh[bi], bU + off);
                ldsm_x4(bl[bi], bU + BPLANE + off);
            }
#pragma unroll
            for (int mi = 0; mi < 2; mi++)
#pragma unroll
                for (int ni = 0; ni < 4; ni++) {
                    uint32_t h0 = bh[ni >> 1][(ni & 1) * 2];
                    uint32_t h1 = bh[ni >> 1][(ni & 1) * 2 + 1];
                    uint32_t l0 = bl[ni >> 1][(ni & 1) * 2];
                    uint32_t l1 = bl[ni >> 1][(ni & 1) * 2 + 1];
                    mma_f16(acc[mi][ni], ah[mi], h0, h1);
                    mma_f16(acc[mi][ni], ah[mi], l0, l1);
                    mma_f16(acc[mi][ni], al[mi], h0, h1);
                }
        }
        __syncthreads();
    }

    const int gr = lane >> 2;
    const int gc = (lane & 3) * 2;
#pragma unroll
    for (int mi = 0; mi < 2; mi++) {
        int r0 = bm + m0 + mi * 16 + gr;
#pragma unroll
        for (int ni = 0; ni < 4; ni++) {
            int c = bn + n0 + ni * 8 + gc;
            if (c + 1 < N) {
                *(float2*)(C + (size_t)r0 * N + c) =
                    make_float2(acc[mi][ni][0] + bias[c], acc[mi][ni][1] + bias[c + 1]);
                *(float2*)(C + (size_t)(r0 + 8) * N + c) =
                    make_float2(acc[mi][ni][2] + bias[c], acc[mi][ni][3] + bias[c + 1]);
            } else if (c < N) {
                C[(size_t)r0 * N + c] = acc[mi][ni][0] + bias[c];
                C[(size_t)(r0 + 8) * N + c] = acc[mi][ni][2] + bias[c];
            }
        }
    }
}

// ====== fused GEMM (N=256) + bias + residual + LayerNorm (3-stage) ========
// Residual read from XH/XL planes (hi+lo ~= fp32); no fp32 X buffer.
#define LN_BM 64
#define LN_AP 8192
#define LN_BP 32768
#define LN_STAGE (LN_AP + LN_BP)       // 40960
#define LN_SMEM (3*LN_STAGE + 1024)    // 123904

__device__ __forceinline__ void ln_fill(
    uint32_t smU, int b, int kb,
    const __half* __restrict__ AHi, const __half* __restrict__ BHi,
    int K, int bm, int tid)
{
    const int k0 = kb * GKB;
    uint32_t aU = smU + b * LN_STAGE;
    uint32_t bU = aU + LN_AP;
    {
        int row = tid >> 3;
        int ch  = (tid & 7) << 4;
        uint32_t off = swz128((uint32_t)(row * 128 + ch));
        cp_async16(aU + off, (const char*)AHi + ((size_t)(bm + row) * K + k0) * 2 + ch);
    }
#pragma unroll
    for (int i = 0; i < 4; i++) {
        int j   = tid + 512 * i;
        int row = j >> 3;
        int ch  = (j & 7) << 4;
        uint32_t off = swz128((uint32_t)(row * 128 + ch));
        cp_async16(bU + off, (const char*)BHi + ((size_t)row * K + k0) * 2 + ch);
    }
}

__global__ __launch_bounds__(512)
void gemm_ln(const __half* __restrict__ AHi,
             const __half* __restrict__ BHi,
             const float* __restrict__ bias,
             const float* __restrict__ g,
             const float* __restrict__ be,
             __half* __restrict__ XH,
             __half* __restrict__ XL,
             int K)
{
    extern __shared__ char dsm_raw[];
    __shared__ float redS[64][4], redQ[64][4];

    const int tid  = threadIdx.x;
    const int lane = tid & 31;
    const int wid  = tid >> 5;
    const int m0   = (wid >> 2) * 16;
    const int n0   = (wid & 3) * 64;
    const int bm   = blockIdx.x * LN_BM;
    const int nk   = K / GKB;

    uint32_t rawU = smem_u32(dsm_raw);
    uint32_t smU  = (rawU + 1023u) & ~1023u;

    float acc[8][4];
#pragma unroll
    for (int ni = 0; ni < 8; ni++)
#pragma unroll
        for (int e = 0; e < 4; e++) acc[ni][e] = 0.0f;

    ln_fill(smU, 0, 0, AHi, BHi, K, bm, tid);
    cp_commit();
    ln_fill(smU, 1, 1, AHi, BHi, K, bm, tid);
    cp_commit();

    const int a_row = m0 + (lane & 15);
    const int a_kb  = (lane >> 4) * 16;
    const int b_rowL = ((lane >> 4) << 3) + (lane & 7);
    const int b_kb  = ((lane >> 3) & 1) * 16;

    int bf = 0;
    for (int kb = 0; kb < nk; kb++) {
        if (kb + 1 < nk) cp_wait1(); else cp_wait0();
        __syncthreads();
        if (kb + 2 < nk) {
            int nb = bf + 2; if (nb >= 3) nb -= 3;
            ln_fill(smU, nb, kb + 2, AHi, BHi, K, bm, tid);
            cp_commit();
        }

        const uint32_t aU = smU + bf * LN_STAGE;
        const uint32_t bU = aU + LN_AP;
#pragma unroll
        for (int ks = 0; ks < 4; ks++) {
            const int kbase = ks * 32;
            uint32_t ah[4], bh[4][4];
            ldsm_x4(ah, aU + swz128((uint32_t)(a_row * 128 + kbase + a_kb)));
#pragma unroll
            for (int bi = 0; bi < 4; bi++)
                ldsm_x4(bh[bi], bU + swz128((uint32_t)((n0 + bi * 16 + b_rowL) * 128 + kbase + b_kb)));
#pragma unroll
            for (int ni = 0; ni < 8; ni++)
                mma_f16(acc[ni], ah,
                        bh[ni >> 1][(ni & 1) * 2], bh[ni >> 1][(ni & 1) * 2 + 1]);
        }
        if (++bf == 3) bf = 0;
    }

    // ---- epilogue: bias + residual (from hi/lo planes), LN, write ----
    const int gr = lane >> 2;
    const int tg = lane & 3;
    const int nw = wid & 3;

    int rl0 = m0 + gr;
    int rl1 = rl0 + 8;
    size_t gb0 = (size_t)(bm + rl0) * D_;
    size_t gb1 = (size_t)(bm + rl1) * D_;
    {
        float s0 = 0.f, q0 = 0.f, s1 = 0.f, q1 = 0.f;
#pragma unroll
        for (int ni = 0; ni < 8; ni++) {
            int c = n0 + ni * 8 + tg * 2;
            float2 bv = *(const float2*)(bias + c);
            float2 xh0 = h2f2(*(const uint32_t*)(XH + gb0 + c));
            float2 xl0 = h2f2(*(const uint32_t*)(XL + gb0 + c));
            float2 xh1 = h2f2(*(const uint32_t*)(XH + gb1 + c));
            float2 xl1 = h2f2(*(const uint32_t*)(XL + gb1 + c));
            acc[ni][0] += bv.x + xh0.x + xl0.x;
            acc[ni][1] += bv.y + xh0.y + xl0.y;
            acc[ni][2] += bv.x + xh1.x + xl1.x;
            acc[ni][3] += bv.y + xh1.y + xl1.y;
            s0 += acc[ni][0] + acc[ni][1];
            q0 += acc[ni][0] * acc[ni][0] + acc[ni][1] * acc[ni][1];
            s1 += acc[ni][2] + acc[ni][3];
            q1 += acc[ni][2] * acc[ni][2] + acc[ni][3] * acc[ni][3];
        }
#pragma unroll
        for (int o = 1; o <= 2; o <<= 1) {
            s0 += __shfl_xor_sync(0xFFFFFFFFu, s0, o);
            q0 += __shfl_xor_sync(0xFFFFFFFFu, q0, o);
            s1 += __shfl_xor_sync(0xFFFFFFFFu, s1, o);
            q1 += __shfl_xor_sync(0xFFFFFFFFu, q1, o);
        }
        if (tg == 0) {
            redS[rl0][nw] = s0; redQ[rl0][nw] = q0;
            redS[rl1][nw] = s1; redQ[rl1][nw] = q1;
        }
    }
    __syncthreads();

    {
        float S0 = redS[rl0][0] + redS[rl0][1] + redS[rl0][2] + redS[rl0][3];
        float Q0 = redQ[rl0][0] + redQ[rl0][1] + redQ[rl0][2] + redQ[rl0][3];
        float S1 = redS[rl1][0] + redS[rl1][1] + redS[rl1][2] + redS[rl1][3];
        float Q1 = redQ[rl1][0] + redQ[rl1][1] + redQ[rl1][2] + redQ[rl1][3];
        float mean0 = S0 * (1.0f / D_);
        float mean1 = S1 * (1.0f / D_);
        float r0 = rsqrtf(Q0 * (1.0f / D_) - mean0 * mean0 + 1e-5f);
        float r1 = rsqrtf(Q1 * (1.0f / D_) - mean1 * mean1 + 1e-5f);
#pragma unroll
        for (int ni = 0; ni < 8; ni++) {
            int c = n0 + ni * 8 + tg * 2;
            float2 gv = *(const float2*)(g + c);
            float2 bev = *(const float2*)(be + c);
            float o00 = (acc[ni][0] - mean0) * r0 * gv.x + bev.x;
            float o01 = (acc[ni][1] - mean0) * r0 * gv.y + bev.y;
            float o10 = (acc[ni][2] - mean1) * r1 * gv.x + bev.x;
            float o11 = (acc[ni][3] - mean1) * r1 * gv.y + bev.y;
            uint32_t hp, lp;
            split2h(o00, o01, hp, lp);
            *(uint32_t*)(XH + gb0 + c) = hp;
            *(uint32_t*)(XL + gb0 + c) = lp;
            split2h(o10, o11, hp, lp);
            *(uint32_t*)(XH + gb1 + c) = hp;
            *(uint32_t*)(XL + gb1 + c) = lp;
        }
    }
}

// ========== tensor-core causal flash attention (no-max softmax) ===========
// R12 config: 64 queries/CTA, 4 warps x 16 rows, Q pre-scaled, x4 ldsm.
#define AT_PITCH 80
#define AT_Q 0
#define AT_KV 5120
#define AT_BUF 10240
#define AT_SMEM (AT_KV + 3*AT_BUF + 1024)

__device__ __forceinline__ void attn_fill_kv(
    uint32_t smU, int buf,
    const __half* __restrict__ Ph,
    size_t rowbase, int kt, int h, int tid)
{
    uint32_t base = smU + AT_KV + buf * AT_BUF;
#pragma unroll
    for (int i = 0; i < 2; i++) {
        int j = tid + 128 * i;
        int row = j >> 2, ch = (j & 3) * 16;
        size_t gk = ((rowbase + kt + row) * QKV_N + 256 + h * DH_) * 2 + ch;
        size_t gv = gk + 512;
        uint32_t d = row * AT_PITCH + ch;
        cp_async16(base + d,        (const char*)Ph + gk);
        cp_async16(base + 5120 + d, (const char*)Ph + gv);
    }
}

__global__ __launch_bounds__(128)
void attn_tc(const __half* __restrict__ Ph,
             __half* __restrict__ YH,
             const int* __restrict__ tsl)
{
    extern __shared__ char asmem_raw[];
    const int tid = threadIdx.x, lane = tid & 31, w = tid >> 5;
    const int qblk = (gridDim.x - 1) - blockIdx.x;   // longest-first
    const int h = blockIdx.y, b = blockIdx.z;
    const int q0 = qblk * 64;
    const int len = tsl[b];
    const int gr = lane >> 2, tg = lane & 3;
    uint32_t rawU = smem_u32(asmem_raw);
    const uint32_t smU = (rawU + 1023u) & ~1023u;
    const size_t rowbase = (size_t)b * S_;
    const int nt = qblk + 1;

#pragma unroll
    for (int i = 0; i < 2; i++) {
        int jj = tid + 128 * i;
        int row = jj >> 2, ch = (jj & 3) * 16;
        size_t src = ((rowbase + q0 + row) * QKV_N + h * DH_) * 2 + ch;
        cp_async16(smU + AT_Q + row * AT_PITCH + ch, (const char*)Ph + src);
    }
    attn_fill_kv(smU, 0, Ph, rowbase, 0, h, tid);
    cp_commit();
    if (nt > 1) {
        attn_fill_kv(smU, 1, Ph, rowbase, 64, h, tid);
        cp_commit();
        cp_wait1();
    } else {
        cp_wait0();
    }
    __syncthreads();

    uint32_t qf[2][4];
    {
        int r8 = (lane & 7) + ((lane >> 3) & 1) * 8;
        int cb = ((lane >> 4) & 1) * 16;
#pragma unroll
        for (int kk = 0; kk < 2; kk++)
            ldsm_x4(qf[kk], smU + AT_Q + (uint32_t)(w * 16 + r8) * AT_PITCH + kk * 32 + cb);
    }

    float o[4][4];
    float lrow[2] = {0.f, 0.f};
#pragma unroll
    for (int nd = 0; nd < 4; nd++)
#pragma unroll
        for (int e = 0; e < 4; e++) o[nd][e] = 0.f;

    const int qw0 = q0 + w * 16;
    const int l7 = lane & 7;
    const int khb = ((lane >> 3) & 1) * 16;
    const int nsel = (lane >> 4) & 1;
    const int l15 = lane & 15;

    int bf = 0;
    for (int t = 0; t < nt; t++) {
        const int kt = t * 64;
        if (t + 1 < nt) cp_wait1(); else cp_wait0();
        __syncthreads();
        if (t + 2 < nt) {
            int nb = bf + 2; if (nb >= 3) nb -= 3;
            attn_fill_kv(smU, nb, Ph, rowbase, kt + 128, h, tid);
            cp_commit();
        }

        const uint32_t kb = smU + AT_KV + bf * AT_BUF;
        const uint32_t vb = kb + 5120;

        float s[8][4];
#pragma unroll
        for (int ni = 0; ni < 8; ni++)
#pragma unroll
            for (int e = 0; e < 4; e++) s[ni][e] = 0.f;
#pragma unroll
        for (int kk = 0; kk < 2; kk++)
#pragma unroll
            for (int ni = 0; ni < 8; ni += 2) {
                uint32_t kf[4];
                ldsm_x4(kf, kb + (uint32_t)((ni + nsel) * 8 + l7) * AT_PITCH + kk * 32 + khb);
                mma_f16(s[ni],     qf[kk], kf[0], kf[1]);
                mma_f16(s[ni + 1], qf[kk], kf[2], kf[3]);
            }

        if (kt + 63 > qw0 || kt + 64 > len) {
            int r0 = qw0 + gr, r1 = r0 + 8;
#pragma unroll
            for (int ni = 0; ni < 8; ni++) {
                int c0 = kt + ni * 8 + tg * 2, c1 = c0 + 1;
                if (c0 > r0 || c0 >= len) s[ni][0] = -1e30f;
                if (c1 > r0 || c1 >= len) s[ni][1] = -1e30f;
                if (c0 > r1 || c0 >= len) s[ni][2] = -1e30f;
                if (c1 > r1 || c1 >= len) s[ni][3] = -1e30f;
            }
        }

#pragma unroll
        for (int ni = 0; ni < 8; ni++) {
            float p0 = exp2f(s[ni][0]);
            float p1 = exp2f(s[ni][1]);
            float p2 = exp2f(s[ni][2]);
            float p3 = exp2f(s[ni][3]);
            s[ni][0] = p0; s[ni][1] = p1; s[ni][2] = p2; s[ni][3] = p3;
            lrow[0] += p0 + p1;
            lrow[1] += p2 + p3;
        }

#pragma unroll
        for (int j = 0; j < 4; j++) {
            uint32_t pa[4];
            pa[0] = pack_f2h(s[2*j][0],   s[2*j][1]);
            pa[1] = pack_f2h(s[2*j][2],   s[2*j][3]);
            pa[2] = pack_f2h(s[2*j+1][0], s[2*j+1][1]);
            pa[3] = pack_f2h(s[2*j+1][2], s[2*j+1][3]);
#pragma unroll
            for (int nd = 0; nd < 4; nd += 2) {
                uint32_t vf[4];
                ldsm_x4t(vf, vb + (uint32_t)(16 * j + l15) * AT_PITCH + (nd + nsel) * 16);
                mma_f16(o[nd],     pa, vf[0], vf[1]);
                mma_f16(o[nd + 1], pa, vf[2], vf[3]);
            }
        }
        if (++bf == 3) bf = 0;
    }

#pragma unroll
    for (int hh = 0; hh < 2; hh++) {
        float v = lrow[hh];
        v += __shfl_xor_sync(0xFFFFFFFFu, v, 1);
        v += __shfl_xor_sync(0xFFFFFFFFu, v, 2);
        lrow[hh] = v;
    }
    int r0 = qw0 + gr, r1 = r0 + 8;
    float inv0 = (r0 < len && lrow[0] > 0.f) ? 1.0f / lrow[0] : 0.f;
    float inv1 = (r1 < len && lrow[1] > 0.f) ? 1.0f / lrow[1] : 0.f;
#pragma unroll
    for (int nd = 0; nd < 4; nd++) {
        int col = h * DH_ + nd * 8 + tg * 2;
        *(uint32_t*)(YH + (rowbase + r0) * D_ + col) = pack_f2h(o[nd][0] * inv0, o[nd][1] * inv0);
        *(uint32_t*)(YH + (rowbase + r1) * D_ + col) = pack_f2h(o[nd][2] * inv1, o[nd][3] * inv1);
    }
}

// =========================== launcher ====================================
extern "C" void kernel_launch(void* const* d_in, const int* in_sizes, int n_in,
                              void* d_out, int out_size)
{
    const int*   ids = (const int*)  d_in[0];
    const int*   tsl = (const int*)  d_in[1];
    const float* emb = (const float*)d_in[2];
    const float* Wq  = (const float*)d_in[3];
    const float* bq  = (const float*)d_in[4];
    const float* Wk  = (const float*)d_in[5];
    const float* bk  = (const float*)d_in[6];
    const float* Wv  = (const float*)d_in[7];
    const float* bv  = (const float*)d_in[8];
    const float* Wo  = (const float*)d_in[9];
    const float* bo  = (const float*)d_in[10];
    const float* W1  = (const float*)d_in[11];
    const float* b1  = (const float*)d_in[12];
    const float* W2  = (const float*)d_in[13];
    const float* b2  = (const float*)d_in[14];
    const float* g1  = (const float*)d_in[15];
    const float* be1 = (const float*)d_in[16];
    const float* g2  = (const float*)d_in[17];
    const float* be2 = (const float*)d_in[18];
    const float* Wc  = (const float*)d_in[19];
    const float* bc  = (const float*)d_in[20];
    float* out = (float*)d_out;

    float *bqkv;
    cudaGetSymbolAddress((void**)&bqkv, g_bqkv);

    __half *xh, *xl, *yh, *ffh, *qkvh;
    cudaGetSymbolAddress((void**)&xh,  g_xh);
    cudaGetSymbolAddress((void**)&xl,  g_xl);
    cudaGetSymbolAddress((void**)&yh,  g_yh);
    cudaGetSymbolAddress((void**)&ffh, g_ffh);
    cudaGetSymbolAddress((void**)&qkvh, g_qkvh);

    __half *qkvT, *oT, *w1T, *w2T, *wch, *wcl;
    cudaGetSymbolAddress((void**)&qkvT, g_qkvT);
    cudaGetSymbolAddress((void**)&oT,   g_oT);
    cudaGetSymbolAddress((void**)&w1T,  g_1T);
    cudaGetSymbolAddress((void**)&w2T,  g_2T);
    cudaGetSymbolAddress((void**)&wch,  g_cT_hi);
    cudaGetSymbolAddress((void**)&wcl,  g_cT_lo);

    cudaFuncSetAttribute((const void*)gemm_tc,
                         cudaFuncAttributeMaxDynamicSharedMemorySize, GEMM_SMEM);
    cudaFuncSetAttribute((const void*)gemm_cls,
                         cudaFuncAttributeMaxDynamicSharedMemorySize, CLS_SMEM);
    cudaFuncSetAttribute((const void*)gemm_ln,
                         cudaFuncAttributeMaxDynamicSharedMemorySize, LN_SMEM);
    cudaFuncSetAttribute((const void*)attn_tc,
                         cudaFuncAttributeMaxDynamicSharedMemorySize, AT_SMEM);

    prep_kernel<<<PREP_CONV + M_TOK + 3 * L_, dim3(32, 8)>>>(
        Wq, Wk, Wv, Wo, Wc, W1, W2, qkvT, oT, wch, wcl, w1T, w2T,
        ids, emb, bq, bk, bv, bqkv, xh, xl);

    dim3 gQKV(QKV_N / GBN, M_TOK / GBM);
    dim3 gF  (DFF_ / GBN,  M_TOK / GBM);
    dim3 gC  (2,           M_TOK / GBM);
    const int gLN = M_TOK / LN_BM;   // 128

    for (int l = 0; l < L_; l++) {
        size_t qoff  = (size_t)l * QKV_N * D_;
        size_t ooff  = (size_t)l * D_ * D_;
        size_t w1off = (size_t)l * DFF_ * D_;

        gemm_tc<<<gQKV, 256, GEMM_SMEM>>>(xh, qkvT + qoff,
                                          bqkv + l * QKV_N, 0, qkvh, D_, QKV_N, 0, 256);
        attn_tc<<<dim3(S_ / 64, H_, B_), 128, AT_SMEM>>>(qkvh, yh, tsl);

        gemm_ln<<<gLN, 512, LN_SMEM>>>(yh, oT + ooff,
                                       bo + l * D_, g1 + l * D_, be1 + l * D_,
                                       xh, xl, D_);

        gemm_tc<<<gF, 256, GEMM_SMEM>>>(xh, w1T + w1off,
                                        b1 + l * DFF_, 0, ffh, D_, DFF_, 1, 0);

        gemm_ln<<<gLN, 512, LN_SMEM>>>(ffh, w2T + w1off,
                                       b2 + l * D_, g2 + l * D_, be2 + l * D_,
                                       xh, xl, DFF_);
    }

    gemm_cls<<<gC, 256, CLS_SMEM>>>(xh, xl, wch, wcl, bc, out, D_, V_);
}

// round 16
// speedup vs baseline: 1.0434x; 1.0050x over previous
#include <cuda_runtime.h>
#include <cuda_fp16.h>
#include <math.h>
#include <stdint.h>

// Problem constants
#define B_  8
#define S_  1024
#define D_  256
#define H_  8
#define DH_ 32
#define L_  4
#define V_  100
#define DFF_ 1024
#define M_TOK (B_ * S_)   // 8192
#define QKV_N 768

#define SCL2E 0.2550348243f   // log2(e)/sqrt(32)

// -------- scratch (static device globals; no runtime allocation) --------
__device__ __half g_xh  [M_TOK * D_],  g_xl[M_TOK * D_];
__device__ __half g_yh  [M_TOK * D_];
__device__ __half g_ffh [M_TOK * DFF_];
__device__ __half g_qkvh[M_TOK * QKV_N];

__device__ __half g_qkvT[L_*QKV_N*D_];
__device__ __half g_oT  [L_*D_*D_];
__device__ __half g_1T  [L_*DFF_*D_];
__device__ __half g_2T  [L_*D_*DFF_];
__device__ __half g_cT_hi[128*D_], g_cT_lo[128*D_];
__device__ float g_bqkv[L_ * QKV_N];

// =========================== PTX helpers ==================================
__device__ __forceinline__ uint32_t smem_u32(const void* p) {
    uint32_t r;
    asm("{ .reg .u64 t; cvta.to.shared.u64 t, %1; cvt.u32.u64 %0, t; }"
        : "=r"(r) : "l"(p));
    return r;
}
__device__ __forceinline__ void cp_async16(uint32_t dst, const void* src) {
    asm volatile("cp.async.cg.shared.global [%0], [%1], 16;"
                 :: "r"(dst), "l"(src));
}
__device__ __forceinline__ void cp_commit() {
    asm volatile("cp.async.commit_group;" ::: "memory");
}
__device__ __forceinline__ void cp_wait1() {
    asm volatile("cp.async.wait_group 1;" ::: "memory");
}
__device__ __forceinline__ void cp_wait0() {
    asm volatile("cp.async.wait_group 0;" ::: "memory");
}
__device__ __forceinline__ void ldsm_x4(uint32_t* r, uint32_t addr) {
    asm volatile("ldmatrix.sync.aligned.m8n8.x4.shared.b16 {%0,%1,%2,%3}, [%4];"
                 : "=r"(r[0]), "=r"(r[1]), "=r"(r[2]), "=r"(r[3]) : "r"(addr));
}
__device__ __forceinline__ void ldsm_x4t(uint32_t* r, uint32_t addr) {
    asm volatile("ldmatrix.sync.aligned.m8n8.x4.trans.shared.b16 {%0,%1,%2,%3}, [%4];"
                 : "=r"(r[0]), "=r"(r[1]), "=r"(r[2]), "=r"(r[3]) : "r"(addr));
}
__device__ __forceinline__ void mma_f16(float* d, const uint32_t* a,
                                        uint32_t b0, uint32_t b1) {
    asm volatile(
        "mma.sync.aligned.m16n8k16.row.col.f32.f16.f16.f32 "
        "{%0,%1,%2,%3}, {%4,%5,%6,%7}, {%8,%9}, {%0,%1,%2,%3};"
        : "+f"(d[0]), "+f"(d[1]), "+f"(d[2]), "+f"(d[3])
        : "r"(a[0]), "r"(a[1]), "r"(a[2]), "r"(a[3]), "r"(b0), "r"(b1));
}
__device__ __forceinline__ uint32_t swz128(uint32_t x) {
    return x ^ ((x >> 3) & 0x70u);
}
__device__ __forceinline__ uint32_t pack_h2(__half a, __half b) {
    __half2 t(a, b);
    return *reinterpret_cast<uint32_t*>(&t);
}
__device__ __forceinline__ uint32_t pack_f2h(float a, float b) {
    __half2 t = __floats2half2_rn(a, b);
    return *reinterpret_cast<uint32_t*>(&t);
}
__device__ __forceinline__ void split2h(float a, float b, uint32_t& hi, uint32_t& lo) {
    __half h0 = __float2half_rn(a);
    __half h1 = __float2half_rn(b);
    __half l0 = __float2half_rn(a - __half2float(h0));
    __half l1 = __float2half_rn(b - __half2float(h1));
    hi = pack_h2(h0, h1);
    lo = pack_h2(l0, l1);
}
__device__ __forceinline__ float2 h2f2(uint32_t u) {
    __half2 t = *reinterpret_cast<__half2*>(&u);
    return __half22float2(t);
}

// ===================== GEMM tiling constants ==============================
#define GBM 128
#define GBN 64
#define GKB 64
#define APLANE 16384
#define BPLANE 8192
#define BUFB (APLANE + BPLANE)
#define GEMM_SMEM (3*BUFB + 1024)
#define CLS_BUFB (2*APLANE + 2*BPLANE)
#define CLS_SMEM (2*CLS_BUFB + 1024)

// ===== merged prep: weight transpose/convert + embed + bias pack ==========
#define PREP_CONV 3104
__global__ void prep_kernel(const float* __restrict__ Wq,
                            const float* __restrict__ Wk,
                            const float* __restrict__ Wv,
                            const float* __restrict__ Wo,
                            const float* __restrict__ Wc,
                            const float* __restrict__ W1,
                            const float* __restrict__ W2,
                            __half* __restrict__ qkvT,
                            __half* __restrict__ oT,
                            __half* __restrict__ cH,
                            __half* __restrict__ cL,
                            __half* __restrict__ w1T,
                            __half* __restrict__ w2T,
                            const int* __restrict__ ids,
                            const float* __restrict__ emb,
                            const float* __restrict__ bq,
                            const float* __restrict__ bk,
                            const float* __restrict__ bv,
                            float* __restrict__ bqkv,
                            __half* __restrict__ XH,
                            __half* __restrict__ XL)
{
    const int tb = blockIdx.x;
    const int tx = threadIdx.x, ty = threadIdx.y;

    if (tb >= PREP_CONV) {
        int t = tb - PREP_CONV;
        int d = ty * 32 + tx;
        if (t >= M_TOK) {
            int idx = t - M_TOK;
            int l = idx / 3, seg = idx % 3;
            const float* src = (seg == 0) ? bq : (seg == 1) ? bk : bv;
            bqkv[l * QKV_N + seg * 256 + d] = src[l * 256 + d];
            return;
        }
        int s = t & (S_ - 1);
        int id = ids[t];
        float f = (d < D_ / 2) ? (2.0f * d) : (2.0f * (d - D_ / 2) + 1.0f);
        float inv = exp2f(-f * 13.287712379549449f / (float)D_);
        float v = emb[(size_t)id * D_ + d] + sinf((float)s * inv);
        size_t idx = (size_t)t * D_ + d;
        __half h = __float2half_rn(v);
        XH[idx] = h;
        XL[idx] = __float2half_rn(v - __half2float(h));
        return;
    }

    __shared__ float t[32][33];
    const float* W;
    __half* H;
    int K, N, Nv, kx, ny;
    bool cls = false;
    if (tb < 768) {
        int mat = tb >> 6, w = tb & 63;
        int src = mat >> 2, l = mat & 3;
        W = ((src == 0) ? Wq : (src == 1) ? Wk : Wv) + (size_t)l * D_ * D_;
        H = qkvT + (size_t)l * QKV_N * D_ + (size_t)src * 256 * D_;
        K = 256; N = 256; Nv = 256; kx = w & 7; ny = w >> 3;
    } else if (tb < 1024) {
        int u = tb - 768; int l = u >> 6, w = u & 63;
        W = Wo + (size_t)l * D_ * D_; H = oT + (size_t)l * D_ * D_;
        K = 256; N = 256; Nv = 256; kx = w & 7; ny = w >> 3;
    } else if (tb < 1056) {
        int u = tb - 1024; kx = u & 7; ny = u >> 3;
        W = Wc; H = cH; K = 256; N = V_; Nv = V_; cls = true;
    } else if (tb < 2080) {
        int u = tb - 1056; int mat = u >> 8, w = u & 255;
        W = W1 + (size_t)mat * D_ * DFF_; H = w1T + (size_t)mat * DFF_ * D_;
        K = 256; N = 1024; Nv = 1024; kx = w & 7; ny = w >> 3;
    } else {
        int u = tb - 2080; int mat = u >> 8, w = u & 255;
        W = W2 + (size_t)mat * DFF_ * D_; H = w2T + (size_t)mat * D_ * DFF_;
        K = 1024; N = 256; Nv = 256; kx = w & 31; ny = w >> 5;
    }
    const int k0 = kx * 32, n0 = ny * 32;
#pragma unroll
    for (int r = 0; r < 4; r++) {
        int n = n0 + tx;
        t[ty + 8 * r][tx] = (n < Nv) ? W[(size_t)(k0 + ty + 8 * r) * N + n] : 0.0f;
    }
    __syncthreads();
    if (!cls) {
#pragma unroll
        for (int r = 0; r < 4; r++)
            H[(size_t)(n0 + ty + 8 * r) * K + k0 + tx] =
                __float2half_rn(t[tx][ty + 8 * r]);
    } else {
#pragma unroll
        for (int r = 0; r < 4; r++) {
            float v = t[tx][ty + 8 * r];
            __half h = __float2half_rn(v);
            size_t o = (size_t)(n0 + ty + 8 * r) * 256 + k0 + tx;
            cH[o] = h;
            cL[o] = __float2half_rn(v - __half2float(h));
        }
    }
}

// ================== HMMA fp16 single-pass GEMM (3-stage) ==================
__device__ __forceinline__ void gemm_fill(
    uint32_t smU, int b, int kb,
    const __half* __restrict__ AHi, const __half* __restrict__ BHi,
    int K, int bm, int bn, int tid)
{
    const int k0 = kb * GKB;
    uint32_t aU = smU + b * BUFB;
    uint32_t bU = aU + APLANE;
#pragma unroll
    for (int i = 0; i < 4; i++) {
        int j   = tid + 256 * i;
        int row = j >> 3;
        int ch  = (j & 7) << 4;
        uint32_t off = swz128((uint32_t)(row * 128 + ch));
        cp_async16(aU + off, (const char*)AHi + ((size_t)(bm + row) * K + k0) * 2 + ch);
    }
#pragma unroll
    for (int i = 0; i < 2; i++) {
        int j   = tid + 256 * i;
        int row = j >> 3;
        int ch  = (j & 7) << 4;
        uint32_t off = swz128((uint32_t)(row * 128 + ch));
        cp_async16(bU + off, (const char*)BHi + ((size_t)(bn + row) * K + k0) * 2 + ch);
    }
}

__global__ __launch_bounds__(256, 3)
void gemm_tc(const __half* __restrict__ AHi,
             const __half* __restrict__ BHi,
             const float* __restrict__ bias,
             float* __restrict__ C,
             __half* __restrict__ CHi,
             int K, int N, int relu, int qcols)
{
    extern __shared__ char dsm_raw[];
    const int tid  = threadIdx.x;
    const int lane = tid & 31;
    const int wid  = tid >> 5;
    const int m0   = (wid >> 1) * 32;
    const int n0   = (wid & 1) * 32;
    const int bm   = blockIdx.y * GBM;
    const int bn   = blockIdx.x * GBN;
    const int nk   = K / GKB;

    uint32_t rawU = smem_u32(dsm_raw);
    uint32_t smU  = (rawU + 1023u) & ~1023u;

    float acc[2][4][4];
#pragma unroll
    for (int mi = 0; mi < 2; mi++)
#pragma unroll
        for (int ni = 0; ni < 4; ni++)
#pragma unroll
            for (int e = 0; e < 4; e++) acc[mi][ni][e] = 0.0f;

    gemm_fill(smU, 0, 0, AHi, BHi, K, bm, bn, tid);
    cp_commit();
    gemm_fill(smU, 1, 1, AHi, BHi, K, bm, bn, tid);
    cp_commit();

    const int a_row = m0 + (lane & 15);
    const int a_kb  = (lane >> 4) * 16;
    const int b_row = n0 + ((lane >> 4) << 3) + (lane & 7);
    const int b_kb  = ((lane >> 3) & 1) * 16;

    int bf = 0;
    for (int kb = 0; kb < nk; kb++) {
        if (kb + 1 < nk) cp_wait1(); else cp_wait0();
        __syncthreads();
        if (kb + 2 < nk) {
            int nb = bf + 2; if (nb >= 3) nb -= 3;
            gemm_fill(smU, nb, kb + 2, AHi, BHi, K, bm, bn, tid);
            cp_commit();
        }

        const uint32_t aU = smU + bf * BUFB;
        const uint32_t bU = aU + APLANE;
#pragma unroll
        for (int ks = 0; ks < 4; ks++) {
            const int kbase = ks * 32;
            uint32_t ah[2][4], bh[2][4];
#pragma unroll
            for (int mi = 0; mi < 2; mi++)
                ldsm_x4(ah[mi], aU + swz128((uint32_t)((a_row + mi * 16) * 128 + kbase + a_kb)));
#pragma unroll
            for (int bi = 0; bi < 2; bi++)
                ldsm_x4(bh[bi], bU + swz128((uint32_t)((b_row + bi * 16) * 128 + kbase + b_kb)));
#pragma unroll
            for (int mi = 0; mi < 2; mi++)
#pragma unroll
                for (int ni = 0; ni < 4; ni++)
                    mma_f16(acc[mi][ni], ah[mi],
                            bh[ni >> 1][(ni & 1) * 2], bh[ni >> 1][(ni & 1) * 2 + 1]);
        }
        if (++bf == 3) bf = 0;
    }

    const int gr = lane >> 2;
    const int gc = (lane & 3) * 2;
#pragma unroll
    for (int mi = 0; mi < 2; mi++) {
        int r0 = bm + m0 + mi * 16 + gr;
#pragma unroll
        for (int ni = 0; ni < 4; ni++) {
            int c = bn + n0 + ni * 8 + gc;
            int c0s = (c < N) ? c : N - 1;
            int c1s = (c + 1 < N) ? c + 1 : N - 1;
            float v00 = acc[mi][ni][0] + bias[c0s];
            float v01 = acc[mi][ni][1] + bias[c1s];
            float v10 = acc[mi][ni][2] + bias[c0s];
            float v11 = acc[mi][ni][3] + bias[c1s];
            if (relu) {
                v00 = fmaxf(v00, 0.f); v01 = fmaxf(v01, 0.f);
                v10 = fmaxf(v10, 0.f); v11 = fmaxf(v11, 0.f);
            }
            if (CHi) {
                if (c < qcols) {
                    v00 *= SCL2E; v01 *= SCL2E; v10 *= SCL2E; v11 *= SCL2E;
                }
                *(uint32_t*)(CHi + (size_t)r0 * N + c) = pack_f2h(v00, v01);
                *(uint32_t*)(CHi + (size_t)(r0 + 8) * N + c) = pack_f2h(v10, v11);
            } else if (c + 1 < N) {
                *(float2*)(C + (size_t)r0 * N + c) = make_float2(v00, v01);
                *(float2*)(C + (size_t)(r0 + 8) * N + c) = make_float2(v10, v11);
            } else if (c < N) {
                C[(size_t)r0 * N + c] = v00;
                C[(size_t)(r0 + 8) * N + c] = v10;
            }
        }
    }
}

// ============= classifier GEMM: 3-pass split precision ====================
__device__ __forceinline__ void cls_fill(
    uint32_t smU, int b, int kb,
    const __half* __restrict__ AHi, const __half* __restrict__ ALo,
    const __half* __restrict__ BHi, const __half* __restrict__ BLo,
    int K, int bm, int bn, int tid)
{
    const int k0 = kb * GKB;
    uint32_t aHiU = smU + b * CLS_BUFB;
    uint32_t aLoU = aHiU + APLANE;
    uint32_t bHiU = aHiU + 2 * APLANE;
    uint32_t bLoU = bHiU + BPLANE;
#pragma unroll
    for (int i = 0; i < 4; i++) {
        int j   = tid + 256 * i;
        int row = j >> 3;
        int ch  = (j & 7) << 4;
        uint32_t off = swz128((uint32_t)(row * 128 + ch));
        size_t srcb = ((size_t)(bm + row) * K + k0) * 2 + ch;
        cp_async16(aHiU + off, (const char*)AHi + srcb);
        cp_async16(aLoU + off, (const char*)ALo + srcb);
    }
#pragma unroll
    for (int i = 0; i < 2; i++) {
        int j   = tid + 256 * i;
        int row = j >> 3;
        int ch  = (j & 7) << 4;
        uint32_t off = swz128((uint32_t)(row * 128 + ch));
        size_t srcb = ((size_t)(bn + row) * K + k0) * 2 + ch;
        cp_async16(bHiU + off, (const char*)BHi + srcb);
        cp_async16(bLoU + off, (const char*)BLo + srcb);
    }
}

__global__ __launch_bounds__(256, 2)
void gemm_cls(const __half* __restrict__ AHi,
              const __half* __restrict__ ALo,
              const __half* __restrict__ BHi,
              const __half* __restrict__ BLo,
              const float* __restrict__ bias,
              float* __restrict__ C,
              int K, int N)
{
    extern __shared__ char dsm_raw[];
    const int tid  = threadIdx.x;
    const int lane = tid & 31;
    const int wid  = tid >> 5;
    const int m0   = (wid >> 1) * 32;
    const int n0   = (wid & 1) * 32;
    const int bm   = blockIdx.y * GBM;
    const int bn   = blockIdx.x * GBN;
    const int nk   = K / GKB;

    uint32_t rawU = smem_u32(dsm_raw);
    uint32_t smU  = (rawU + 1023u) & ~1023u;

    float acc[2][4][4];
#pragma unroll
    for (int mi = 0; mi < 2; mi++)
#pragma unroll
        for (int ni = 0; ni < 4; ni++)
#pragma unroll
            for (int e = 0; e < 4; e++) acc[mi][ni][e] = 0.0f;

    cls_fill(smU, 0, 0, AHi, ALo, BHi, BLo, K, bm, bn, tid);
    cp_commit();

    const int a_row = m0 + (lane & 15);
    const int a_kb  = (lane >> 4) * 16;
    const int b_row = n0 + ((lane >> 4) << 3) + (lane & 7);
    const int b_kb  = ((lane >> 3) & 1) * 16;

    for (int kb = 0; kb < nk; kb++) {
        const int b = kb & 1;
        if (kb + 1 < nk) {
            cls_fill(smU, b ^ 1, kb + 1, AHi, ALo, BHi, BLo, K, bm, bn, tid);
            cp_commit();
            cp_wait1();
        } else {
            cp_wait0();
        }
        __syncthreads();

        const uint32_t aU = smU + b * CLS_BUFB;
        const uint32_t bU = aU + 2 * APLANE;
#pragma unroll
        for (int ks = 0; ks < 4; ks++) {
            const int kbase = ks * 32;
            uint32_t ah[2][4], al[2][4], bh[2][4], bl[2][4];
#pragma unroll
            for (int mi = 0; mi < 2; mi++) {
                uint32_t off = swz128((uint32_t)((a_row + mi * 16) * 128 + kbase + a_kb));
                ldsm_x4(ah[mi], aU + off);
                ldsm_x4(al[mi], aU + APLANE + off);
            }
#pragma unroll
            for (int bi = 0; bi < 2; bi++) {
                uint32_t off = swz128((uint32_t)((b_row + bi * 16) * 128 + kbase + b_kb));
                ldsm_x4(bh[bi], bU + off);
                ldsm_x4(bl[bi], bU + BPLANE + off);
            }
#pragma unroll
            for (int mi = 0; mi < 2; mi++)
#pragma unroll
                for (int ni = 0; ni < 4; ni++) {
                    uint32_t h0 = bh[ni >> 1][(ni & 1) * 2];
                    uint32_t h1 = bh[ni >> 1][(ni & 1) * 2 + 1];
                    uint32_t l0 = bl[ni >> 1][(ni & 1) * 2];
                    uint32_t l1 = bl[ni >> 1][(ni & 1) * 2 + 1];
                    mma_f16(acc[mi][ni], ah[mi], h0, h1);
                    mma_f16(acc[mi][ni], ah[mi], l0, l1);
                    mma_f16(acc[mi][ni], al[mi], h0, h1);
                }
        }
        __syncthreads();
    }

    const int gr = lane >> 2;
    const int gc = (lane & 3) * 2;
#pragma unroll
    for (int mi = 0; mi < 2; mi++) {
        int r0 = bm + m0 + mi * 16 + gr;
#pragma unroll
        for (int ni = 0; ni < 4; ni++) {
            int c = bn + n0 + ni * 8 + gc;
            if (c + 1 < N) {
                *(float2*)(C + (size_t)r0 * N + c) =
                    make_float2(acc[mi][ni][0] + bias[c], acc[mi][ni][1] + bias[c + 1]);
                *(float2*)(C + (size_t)(r0 + 8) * N + c) =
                    make_float2(acc[mi][ni][2] + bias[c], acc[mi][ni][3] + bias[c + 1]);
            } else if (c < N) {
                C[(size_t)r0 * N + c] = acc[mi][ni][0] + bias[c];
                C[(size_t)(r0 + 8) * N + c] = acc[mi][ni][2] + bias[c];
            }
        }
    }
}

// ====== fused GEMM (N=256) + bias + residual + LayerNorm (3-stage) ========
// Residual prefetched from XH/XL planes at kernel start (hides LDG latency
// behind the mainloop); each CTA touches only its own rows, so no hazard.
#define LN_BM 64
#define LN_AP 8192
#define LN_BP 32768
#define LN_STAGE (LN_AP + LN_BP)       // 40960
#define LN_SMEM (3*LN_STAGE + 1024)    // 123904

__device__ __forceinline__ void ln_fill(
    uint32_t smU, int b, int kb,
    const __half* __restrict__ AHi, const __half* __restrict__ BHi,
    int K, int bm, int tid)
{
    const int k0 = kb * GKB;
    uint32_t aU = smU + b * LN_STAGE;
    uint32_t bU = aU + LN_AP;
    {
        int row = tid >> 3;
        int ch  = (tid & 7) << 4;
        uint32_t off = swz128((uint32_t)(row * 128 + ch));
        cp_async16(aU + off, (const char*)AHi + ((size_t)(bm + row) * K + k0) * 2 + ch);
    }
#pragma unroll
    for (int i = 0; i < 4; i++) {
        int j   = tid + 512 * i;
        int row = j >> 3;
        int ch  = (j & 7) << 4;
        uint32_t off = swz128((uint32_t)(row * 128 + ch));
        cp_async16(bU + off, (const char*)BHi + ((size_t)row * K + k0) * 2 + ch);
    }
}

__global__ __launch_bounds__(512)
void gemm_ln(const __half* __restrict__ AHi,
             const __half* __restrict__ BHi,
             const float* __restrict__ bias,
             const float* __restrict__ g,
             const float* __restrict__ be,
             __half* __restrict__ XH,
             __half* __restrict__ XL,
             int K)
{
    extern __shared__ char dsm_raw[];
    __shared__ float redS[64][4], redQ[64][4];

    const int tid  = threadIdx.x;
    const int lane = tid & 31;
    const int wid  = tid >> 5;
    const int m0   = (wid >> 2) * 16;
    const int n0   = (wid & 3) * 64;
    const int bm   = blockIdx.x * LN_BM;
    const int nk   = K / GKB;

    uint32_t rawU = smem_u32(dsm_raw);
    uint32_t smU  = (rawU + 1023u) & ~1023u;

    float acc[8][4];
#pragma unroll
    for (int ni = 0; ni < 8; ni++)
#pragma unroll
        for (int e = 0; e < 4; e++) acc[ni][e] = 0.0f;

    ln_fill(smU, 0, 0, AHi, BHi, K, bm, tid);
    cp_commit();
    ln_fill(smU, 1, 1, AHi, BHi, K, bm, tid);
    cp_commit();

    // ---- prefetch residual (hi/lo planes) for this thread's output slots ----
    const int gr = lane >> 2;
    const int tg = lane & 3;
    const int rl0 = m0 + gr;
    const int rl1 = rl0 + 8;
    const size_t gb0 = (size_t)(bm + rl0) * D_;
    const size_t gb1 = (size_t)(bm + rl1) * D_;
    uint32_t rxh0[8], rxl0[8], rxh1[8], rxl1[8];
#pragma unroll
    for (int ni = 0; ni < 8; ni++) {
        int c = n0 + ni * 8 + tg * 2;
        rxh0[ni] = *(const uint32_t*)(XH + gb0 + c);
        rxl0[ni] = *(const uint32_t*)(XL + gb0 + c);
        rxh1[ni] = *(const uint32_t*)(XH + gb1 + c);
        rxl1[ni] = *(const uint32_t*)(XL + gb1 + c);
    }

    const int a_row = m0 + (lane & 15);
    const int a_kb  = (lane >> 4) * 16;
    const int b_rowL = ((lane >> 4) << 3) + (lane & 7);
    const int b_kb  = ((lane >> 3) & 1) * 16;

    int bf = 0;
    for (int kb = 0; kb < nk; kb++) {
        if (kb + 1 < nk) cp_wait1(); else cp_wait0();
        __syncthreads();
        if (kb + 2 < nk) {
            int nb = bf + 2; if (nb >= 3) nb -= 3;
            ln_fill(smU, nb, kb + 2, AHi, BHi, K, bm, tid);
            cp_commit();
        }

        const uint32_t aU = smU + bf * LN_STAGE;
        const uint32_t bU = aU + LN_AP;
#pragma unroll
        for (int ks = 0; ks < 4; ks++) {
            const int kbase = ks * 32;
            uint32_t ah[4], bh[4][4];
            ldsm_x4(ah, aU + swz128((uint32_t)(a_row * 128 + kbase + a_kb)));
#pragma unroll
            for (int bi = 0; bi < 4; bi++)
                ldsm_x4(bh[bi], bU + swz128((uint32_t)((n0 + bi * 16 + b_rowL) * 128 + kbase + b_kb)));
#pragma unroll
            for (int ni = 0; ni < 8; ni++)
                mma_f16(acc[ni], ah,
                        bh[ni >> 1][(ni & 1) * 2], bh[ni >> 1][(ni & 1) * 2 + 1]);
        }
        if (++bf == 3) bf = 0;
    }

    // ---- epilogue: bias + prefetched residual, row stats, LN, write ----
    const int nw = wid & 3;
    {
        float s0 = 0.f, q0 = 0.f, s1 = 0.f, q1 = 0.f;
#pragma unroll
        for (int ni = 0; ni < 8; ni++) {
            int c = n0 + ni * 8 + tg * 2;
            float2 bv = *(const float2*)(bias + c);
            float2 xh0 = h2f2(rxh0[ni]);
            float2 xl0 = h2f2(rxl0[ni]);
            float2 xh1 = h2f2(rxh1[ni]);
            float2 xl1 = h2f2(rxl1[ni]);
            acc[ni][0] += bv.x + xh0.x + xl0.x;
            acc[ni][1] += bv.y + xh0.y + xl0.y;
            acc[ni][2] += bv.x + xh1.x + xl1.x;
            acc[ni][3] += bv.y + xh1.y + xl1.y;
            s0 += acc[ni][0] + acc[ni][1];
            q0 += acc[ni][0] * acc[ni][0] + acc[ni][1] * acc[ni][1];
            s1 += acc[ni][2] + acc[ni][3];
            q1 += acc[ni][2] * acc[ni][2] + acc[ni][3] * acc[ni][3];
        }
#pragma unroll
        for (int o = 1; o <= 2; o <<= 1) {
            s0 += __shfl_xor_sync(0xFFFFFFFFu, s0, o);
            q0 += __shfl_xor_sync(0xFFFFFFFFu, q0, o);
            s1 += __shfl_xor_sync(0xFFFFFFFFu, s1, o);
            q1 += __shfl_xor_sync(0xFFFFFFFFu, q1, o);
        }
        if (tg == 0) {
            redS[rl0][nw] = s0; redQ[rl0][nw] = q0;
            redS[rl1][nw] = s1; redQ[rl1][nw] = q1;
        }
    }
    __syncthreads();

    {
        float S0 = redS[rl0][0] + redS[rl0][1] + redS[rl0][2] + redS[rl0][3];
        float Q0 = redQ[rl0][0] + redQ[rl0][1] + redQ[rl0][2] + redQ[rl0][3];
        float S1 = redS[rl1][0] + redS[rl1][1] + redS[rl1][2] + redS[rl1][3];
        float Q1 = redQ[rl1][0] + redQ[rl1][1] + redQ[rl1][2] + redQ[rl1][3];
        float mean0 = S0 * (1.0f / D_);
        float mean1 = S1 * (1.0f / D_);
        float r0 = rsqrtf(Q0 * (1.0f / D_) - mean0 * mean0 + 1e-5f);
        float r1 = rsqrtf(Q1 * (1.0f / D_) - mean1 * mean1 + 1e-5f);
#pragma unroll
        for (int ni = 0; ni < 8; ni++) {
            int c = n0 + ni * 8 + tg * 2;
            float2 gv = *(const float2*)(g + c);
            float2 bev = *(const float2*)(be + c);
            float o00 = (acc[ni][0] - mean0) * r0 * gv.x + bev.x;
            float o01 = (acc[ni][1] - mean0) * r0 * gv.y + bev.y;
            float o10 = (acc[ni][2] - mean1) * r1 * gv.x + bev.x;
            float o11 = (acc[ni][3] - mean1) * r1 * gv.y + bev.y;
            uint32_t hp, lp;
            split2h(o00, o01, hp, lp);
            *(uint32_t*)(XH + gb0 + c) = hp;
            *(uint32_t*)(XL + gb0 + c) = lp;
            split2h(o10, o11, hp, lp);
            *(uint32_t*)(XH + gb1 + c) = hp;
            *(uint32_t*)(XL + gb1 + c) = lp;
        }
    }
}

// ========== tensor-core causal flash attention (no-max softmax) ===========
// 64 queries/CTA, 4 warps x 16 rows, Q pre-scaled, x4 ldsm.
#define AT_PITCH 80
#define AT_Q 0
#define AT_KV 5120
#define AT_BUF 10240
#define AT_SMEM (AT_KV + 3*AT_BUF + 1024)

__device__ __forceinline__ void attn_fill_kv(
    uint32_t smU, int buf,
    const __half* __restrict__ Ph,
    size_t rowbase, int kt, int h, int tid)
{
    uint32_t base = smU + AT_KV + buf * AT_BUF;
#pragma unroll
    for (int i = 0; i < 2; i++) {
        int j = tid + 128 * i;
        int row = j >> 2, ch = (j & 3) * 16;
        size_t gk = ((rowbase + kt + row) * QKV_N + 256 + h * DH_) * 2 + ch;
        size_t gv = gk + 512;
        uint32_t d = row * AT_PITCH + ch;
        cp_async16(base + d,        (const char*)Ph + gk);
        cp_async16(base + 5120 + d, (const char*)Ph + gv);
    }
}

__global__ __launch_bounds__(128)
void attn_tc(const __half* __restrict__ Ph,
             __half* __restrict__ YH,
             const int* __restrict__ tsl)
{
    extern __shared__ char asmem_raw[];
    const int tid = threadIdx.x, lane = tid & 31, w = tid >> 5;
    const int qblk = (gridDim.x - 1) - blockIdx.x;   // longest-first
    const int h = blockIdx.y, b = blockIdx.z;
    const int q0 = qblk * 64;
    const int len = tsl[b];
    const int gr = lane >> 2, tg = lane & 3;
    uint32_t rawU = smem_u32(asmem_raw);
    const uint32_t smU = (rawU + 1023u) & ~1023u;
    const size_t rowbase = (size_t)b * S_;
    const int nt = qblk + 1;

#pragma unroll
    for (int i = 0; i < 2; i++) {
        int jj = tid + 128 * i;
        int row = jj >> 2, ch = (jj & 3) * 16;
        size_t src = ((rowbase + q0 + row) * QKV_N + h * DH_) * 2 + ch;
        cp_async16(smU + AT_Q + row * AT_PITCH + ch, (const char*)Ph + src);
    }
    attn_fill_kv(smU, 0, Ph, rowbase, 0, h, tid);
    cp_commit();
    if (nt > 1) {
        attn_fill_kv(smU, 1, Ph, rowbase, 64, h, tid);
        cp_commit();
        cp_wait1();
    } else {
        cp_wait0();
    }
    __syncthreads();

    uint32_t qf[2][4];
    {
        int r8 = (lane & 7) + ((lane >> 3) & 1) * 8;
        int cb = ((lane >> 4) & 1) * 16;
#pragma unroll
        for (int kk = 0; kk < 2; kk++)
            ldsm_x4(qf[kk], smU + AT_Q + (uint32_t)(w * 16 + r8) * AT_PITCH + kk * 32 + cb);
    }

    float o[4][4];
    float lrow[2] = {0.f, 0.f};
#pragma unroll
    for (int nd = 0; nd < 4; nd++)
#pragma unroll
        for (int e = 0; e < 4; e++) o[nd][e] = 0.f;

    const int qw0 = q0 + w * 16;
    const int l7 = lane & 7;
    const int khb = ((lane >> 3) & 1) * 16;
    const int nsel = (lane >> 4) & 1;
    const int l15 = lane & 15;

    int bf = 0;
    for (int t = 0; t < nt; t++) {
        const int kt = t * 64;
        if (t + 1 < nt) cp_wait1(); else cp_wait0();
        __syncthreads();
        if (t + 2 < nt) {
            int nb = bf + 2; if (nb >= 3) nb -= 3;
            attn_fill_kv(smU, nb, Ph, rowbase, kt + 128, h, tid);
            cp_commit();
        }

        const uint32_t kb = smU + AT_KV + bf * AT_BUF;
        const uint32_t vb = kb + 5120;

        float s[8][4];
#pragma unroll
        for (int ni = 0; ni < 8; ni++)
#pragma unroll
            for (int e = 0; e < 4; e++) s[ni][e] = 0.f;
#pragma unroll
        for (int kk = 0; kk < 2; kk++)
#pragma unroll
            for (int ni = 0; ni < 8; ni += 2) {
                uint32_t kf[4];
                ldsm_x4(kf, kb + (uint32_t)((ni + nsel) * 8 + l7) * AT_PITCH + kk * 32 + khb);
                mma_f16(s[ni],     qf[kk], kf[0], kf[1]);
                mma_f16(s[ni + 1], qf[kk], kf[2], kf[3]);
            }

        if (kt + 63 > qw0 || kt + 64 > len) {
            int r0 = qw0 + gr, r1 = r0 + 8;
#pragma unroll
            for (int ni = 0; ni < 8; ni++) {
                int c0 = kt + ni * 8 + tg * 2, c1 = c0 + 1;
                if (c0 > r0 || c0 >= len) s[ni][0] = -1e30f;
                if (c1 > r0 || c1 >= len) s[ni][1] = -1e30f;
                if (c0 > r1 || c0 >= len) s[ni][2] = -1e30f;
                if (c1 > r1 || c1 >= len) s[ni][3] = -1e30f;
            }
        }

#pragma unroll
        for (int ni = 0; ni < 8; ni++) {
            float p0 = exp2f(s[ni][0]);
            float p1 = exp2f(s[ni][1]);
            float p2 = exp2f(s[ni][2]);
            float p3 = exp2f(s[ni][3]);
            s[ni][0] = p0; s[ni][1] = p1; s[ni][2] = p2; s[ni][3] = p3;
            lrow[0] += p0 + p1;
            lrow[1] += p2 + p3;
        }

#pragma unroll
        for (int j = 0; j < 4; j++) {
            uint32_t pa[4];
            pa[0] = pack_f2h(s[2*j][0],   s[2*j][1]);
            pa[1] = pack_f2h(s[2*j][2],   s[2*j][3]);
            pa[2] = pack_f2h(s[2*j+1][0], s[2*j+1][1]);
            pa[3] = pack_f2h(s[2*j+1][2], s[2*j+1][3]);
#pragma unroll
            for (int nd = 0; nd < 4; nd += 2) {
                uint32_t vf[4];
                ldsm_x4t(vf, vb + (uint32_t)(16 * j + l15) * AT_PITCH + (nd + nsel) * 16);
                mma_f16(o[nd],     pa, vf[0], vf[1]);
                mma_f16(o[nd + 1], pa, vf[2], vf[3]);
            }
        }
        if (++bf == 3) bf = 0;
    }

#pragma unroll
    for (int hh = 0; hh < 2; hh++) {
        float v = lrow[hh];
        v += __shfl_xor_sync(0xFFFFFFFFu, v, 1);
        v += __shfl_xor_sync(0xFFFFFFFFu, v, 2);
        lrow[hh] = v;
    }
    int r0 = qw0 + gr, r1 = r0 + 8;
    float inv0 = (r0 < len && lrow[0] > 0.f) ? 1.0f / lrow[0] : 0.f;
    float inv1 = (r1 < len && lrow[1] > 0.f) ? 1.0f / lrow[1] : 0.f;
#pragma unroll
    for (int nd = 0; nd < 4; nd++) {
        int col = h * DH_ + nd * 8 + tg * 2;
        *(uint32_t*)(YH + (rowbase + r0) * D_ + col) = pack_f2h(o[nd][0] * inv0, o[nd][1] * inv0);
        *(uint32_t*)(YH + (rowbase + r1) * D_ + col) = pack_f2h(o[nd][2] * inv1, o[nd][3] * inv1);
    }
}

// =========================== launcher ====================================
extern "C" void kernel_launch(void* const* d_in, const int* in_sizes, int n_in,
                              void* d_out, int out_size)
{
    const int*   ids = (const int*)  d_in[0];
    const int*   tsl = (const int*)  d_in[1];
    const float* emb = (const float*)d_in[2];
    const float* Wq  = (const float*)d_in[3];
    const float* bq  = (const float*)d_in[4];
    const float* Wk  = (const float*)d_in[5];
    const float* bk  = (const float*)d_in[6];
    const float* Wv  = (const float*)d_in[7];
    const float* bv  = (const float*)d_in[8];
    const float* Wo  = (const float*)d_in[9];
    const float* bo  = (const float*)d_in[10];
    const float* W1  = (const float*)d_in[11];
    const float* b1  = (const float*)d_in[12];
    const float* W2  = (const float*)d_in[13];
    const float* b2  = (const float*)d_in[14];
    const float* g1  = (const float*)d_in[15];
    const float* be1 = (const float*)d_in[16];
    const float* g2  = (const float*)d_in[17];
    const float* be2 = (const float*)d_in[18];
    const float* Wc  = (const float*)d_in[19];
    const float* bc  = (const float*)d_in[20];
    float* out = (float*)d_out;

    float *bqkv;
    cudaGetSymbolAddress((void**)&bqkv, g_bqkv);

    __half *xh, *xl, *yh, *ffh, *qkvh;
    cudaGetSymbolAddress((void**)&xh,  g_xh);
    cudaGetSymbolAddress((void**)&xl,  g_xl);
    cudaGetSymbolAddress((void**)&yh,  g_yh);
    cudaGetSymbolAddress((void**)&ffh, g_ffh);
    cudaGetSymbolAddress((void**)&qkvh, g_qkvh);

    __half *qkvT, *oT, *w1T, *w2T, *wch, *wcl;
    cudaGetSymbolAddress((void**)&qkvT, g_qkvT);
    cudaGetSymbolAddress((void**)&oT,   g_oT);
    cudaGetSymbolAddress((void**)&w1T,  g_1T);
    cudaGetSymbolAddress((void**)&w2T,  g_2T);
    cudaGetSymbolAddress((void**)&wch,  g_cT_hi);
    cudaGetSymbolAddress((void**)&wcl,  g_cT_lo);

    cudaFuncSetAttribute((const void*)gemm_tc,
                         cudaFuncAttributeMaxDynamicSharedMemorySize, GEMM_SMEM);
    cudaFuncSetAttribute((const void*)gemm_cls,
                         cudaFuncAttributeMaxDynamicSharedMemorySize, CLS_SMEM);
    cudaFuncSetAttribute((const void*)gemm_ln,
                         cudaFuncAttributeMaxDynamicSharedMemorySize, LN_SMEM);
    cudaFuncSetAttribute((const void*)attn_tc,
                         cudaFuncAttributeMaxDynamicSharedMemorySize, AT_SMEM);

    prep_kernel<<<PREP_CONV + M_TOK + 3 * L_, dim3(32, 8)>>>(
        Wq, Wk, Wv, Wo, Wc, W1, W2, qkvT, oT, wch, wcl, w1T, w2T,
        ids, emb, bq, bk, bv, bqkv, xh, xl);

    dim3 gQKV(QKV_N / GBN, M_TOK / GBM);
    dim3 gF  (DFF_ / GBN,  M_TOK / GBM);
    dim3 gC  (2,           M_TOK / GBM);
    const int gLN = M_TOK / LN_BM;   // 128

    for (int l = 0; l < L_; l++) {
        size_t qoff  = (size_t)l * QKV_N * D_;
        size_t ooff  = (size_t)l * D_ * D_;
        size_t w1off = (size_t)l * DFF_ * D_;

        gemm_tc<<<gQKV, 256, GEMM_SMEM>>>(xh, qkvT + qoff,
                                          bqkv + l * QKV_N, 0, qkvh, D_, QKV_N, 0, 256);
        attn_tc<<<dim3(S_ / 64, H_, B_), 128, AT_SMEM>>>(qkvh, yh, tsl);

        gemm_ln<<<gLN, 512, LN_SMEM>>>(yh, oT + ooff,
                                       bo + l * D_, g1 + l * D_, be1 + l * D_,
                                       xh, xl, D_);

        gemm_tc<<<gF, 256, GEMM_SMEM>>>(xh, w1T + w1off,
                                        b1 + l * DFF_, 0, ffh, D_, DFF_, 1, 0);

        gemm_ln<<<gLN, 512, LN_SMEM>>>(ffh, w2T + w1off,
                                       b2 + l * D_, g2 + l * D_, be2 + l * D_,
                                       xh, xl, DFF_);
    }

    gemm_cls<<<gC, 256, CLS_SMEM>>>(xh, xl, wch, wcl, bc, out, D_, V_);
}

// round 17
// speedup vs baseline: 1.0501x; 1.0064x over previous
#include <cuda_runtime.h>
#include <cuda_fp16.h>
#include <math.h>
#include <stdint.h>

// Problem constants
#define B_  8
#define S_  1024
#define D_  256
#define H_  8
#define DH_ 32
#define L_  4
#define V_  100
#define DFF_ 1024
#define M_TOK (B_ * S_)   // 8192
#define QKV_N 768

#define SCL2E 0.2550348243f   // log2(e)/sqrt(32)

// -------- scratch (static device globals; no runtime allocation) --------
__device__ __half g_xh  [M_TOK * D_],  g_xl[M_TOK * D_];
__device__ __half g_yh  [M_TOK * D_];
__device__ __half g_ffh [M_TOK * DFF_];
__device__ __half g_qkvh[M_TOK * QKV_N];

__device__ __half g_qkvT[L_*QKV_N*D_];
__device__ __half g_oT  [L_*D_*D_];
__device__ __half g_1T  [L_*DFF_*D_];
__device__ __half g_2T  [L_*D_*DFF_];
__device__ __half g_cT_hi[128*D_], g_cT_lo[128*D_];
__device__ float g_bqkv[L_ * QKV_N];

// =========================== PTX helpers ==================================
__device__ __forceinline__ uint32_t smem_u32(const void* p) {
    uint32_t r;
    asm("{ .reg .u64 t; cvta.to.shared.u64 t, %1; cvt.u32.u64 %0, t; }"
        : "=r"(r) : "l"(p));
    return r;
}
__device__ __forceinline__ void cp_async16(uint32_t dst, const void* src) {
    asm volatile("cp.async.cg.shared.global [%0], [%1], 16;"
                 :: "r"(dst), "l"(src));
}
__device__ __forceinline__ void cp_commit() {
    asm volatile("cp.async.commit_group;" ::: "memory");
}
__device__ __forceinline__ void cp_wait1() {
    asm volatile("cp.async.wait_group 1;" ::: "memory");
}
__device__ __forceinline__ void cp_wait0() {
    asm volatile("cp.async.wait_group 0;" ::: "memory");
}
__device__ __forceinline__ void ldsm_x4(uint32_t* r, uint32_t addr) {
    asm volatile("ldmatrix.sync.aligned.m8n8.x4.shared.b16 {%0,%1,%2,%3}, [%4];"
                 : "=r"(r[0]), "=r"(r[1]), "=r"(r[2]), "=r"(r[3]) : "r"(addr));
}
__device__ __forceinline__ void ldsm_x4t(uint32_t* r, uint32_t addr) {
    asm volatile("ldmatrix.sync.aligned.m8n8.x4.trans.shared.b16 {%0,%1,%2,%3}, [%4];"
                 : "=r"(r[0]), "=r"(r[1]), "=r"(r[2]), "=r"(r[3]) : "r"(addr));
}
__device__ __forceinline__ void mma_f16(float* d, const uint32_t* a,
                                        uint32_t b0, uint32_t b1) {
    asm volatile(
        "mma.sync.aligned.m16n8k16.row.col.f32.f16.f16.f32 "
        "{%0,%1,%2,%3}, {%4,%5,%6,%7}, {%8,%9}, {%0,%1,%2,%3};"
        : "+f"(d[0]), "+f"(d[1]), "+f"(d[2]), "+f"(d[3])
        : "r"(a[0]), "r"(a[1]), "r"(a[2]), "r"(a[3]), "r"(b0), "r"(b1));
}
__device__ __forceinline__ uint32_t swz128(uint32_t x) {
    return x ^ ((x >> 3) & 0x70u);
}
__device__ __forceinline__ uint32_t pack_h2(__half a, __half b) {
    __half2 t(a, b);
    return *reinterpret_cast<uint32_t*>(&t);
}
__device__ __forceinline__ uint32_t pack_f2h(float a, float b) {
    __half2 t = __floats2half2_rn(a, b);
    return *reinterpret_cast<uint32_t*>(&t);
}
__device__ __forceinline__ void split2h(float a, float b, uint32_t& hi, uint32_t& lo) {
    __half h0 = __float2half_rn(a);
    __half h1 = __float2half_rn(b);
    __half l0 = __float2half_rn(a - __half2float(h0));
    __half l1 = __float2half_rn(b - __half2float(h1));
    hi = pack_h2(h0, h1);
    lo = pack_h2(l0, l1);
}
__device__ __forceinline__ float2 h2f2(uint32_t u) {
    __half2 t = *reinterpret_cast<__half2*>(&u);
    return __half22float2(t);
}

// ===================== GEMM tiling constants ==============================
#define GBM 128
#define GBN 64
#define GKB 64
#define APLANE 16384
#define BPLANE 8192
#define BUFB (APLANE + BPLANE)
#define GEMM_SMEM (3*BUFB + 1024)
#define CLS_BUFB (2*APLANE + 2*BPLANE)
#define CLS_SMEM (2*CLS_BUFB + 1024)

// ===== merged prep: weight transpose/convert + embed (per-s) + bias pack ==
// blocks [0,3104): weight converts
// blocks [3104, 3104+1024): embed, one block per sequence position s
// blocks [3104+1024, 3104+1024+12): bias pack
#define PREP_CONV 3104
#define PREP_EMB  (PREP_CONV + S_)
__global__ void prep_kernel(const float* __restrict__ Wq,
                            const float* __restrict__ Wk,
                            const float* __restrict__ Wv,
                            const float* __restrict__ Wo,
                            const float* __restrict__ Wc,
                            const float* __restrict__ W1,
                            const float* __restrict__ W2,
                            __half* __restrict__ qkvT,
                            __half* __restrict__ oT,
                            __half* __restrict__ cH,
                            __half* __restrict__ cL,
                            __half* __restrict__ w1T,
                            __half* __restrict__ w2T,
                            const int* __restrict__ ids,
                            const float* __restrict__ emb,
                            const float* __restrict__ bq,
                            const float* __restrict__ bk,
                            const float* __restrict__ bv,
                            float* __restrict__ bqkv,
                            __half* __restrict__ XH,
                            __half* __restrict__ XL)
{
    const int tb = blockIdx.x;
    const int tx = threadIdx.x, ty = threadIdx.y;

    if (tb >= PREP_CONV) {
        int d = ty * 32 + tx;
        if (tb >= PREP_EMB) {
            int idx = tb - PREP_EMB;          // 0..3L-1
            int l = idx / 3, seg = idx % 3;
            const float* src = (seg == 0) ? bq : (seg == 1) ? bk : bv;
            bqkv[l * QKV_N + seg * 256 + d] = src[l * 256 + d];
            return;
        }
        // embed: one block per sequence position; PE computed once, reused
        // across all B_ batch rows (identical value per (s,d)).
        int s = tb - PREP_CONV;
        float f = (d < D_ / 2) ? (2.0f * d) : (2.0f * (d - D_ / 2) + 1.0f);
        float inv = exp2f(-f * 13.287712379549449f / (float)D_);
        float pe = sinf((float)s * inv);
#pragma unroll
        for (int b = 0; b < B_; b++) {
            int t = b * S_ + s;
            int id = ids[t];
            float v = emb[(size_t)id * D_ + d] + pe;
            size_t idx = (size_t)t * D_ + d;
            __half h = __float2half_rn(v);
            XH[idx] = h;
            XL[idx] = __float2half_rn(v - __half2float(h));
        }
        return;
    }

    __shared__ float t[32][33];
    const float* W;
    __half* H;
    int K, N, Nv, kx, ny;
    bool cls = false;
    if (tb < 768) {
        int mat = tb >> 6, w = tb & 63;
        int src = mat >> 2, l = mat & 3;
        W = ((src == 0) ? Wq : (src == 1) ? Wk : Wv) + (size_t)l * D_ * D_;
        H = qkvT + (size_t)l * QKV_N * D_ + (size_t)src * 256 * D_;
        K = 256; N = 256; Nv = 256; kx = w & 7; ny = w >> 3;
    } else if (tb < 1024) {
        int u = tb - 768; int l = u >> 6, w = u & 63;
        W = Wo + (size_t)l * D_ * D_; H = oT + (size_t)l * D_ * D_;
        K = 256; N = 256; Nv = 256; kx = w & 7; ny = w >> 3;
    } else if (tb < 1056) {
        int u = tb - 1024; kx = u & 7; ny = u >> 3;
        W = Wc; H = cH; K = 256; N = V_; Nv = V_; cls = true;
    } else if (tb < 2080) {
        int u = tb - 1056; int mat = u >> 8, w = u & 255;
        W = W1 + (size_t)mat * D_ * DFF_; H = w1T + (size_t)mat * DFF_ * D_;
        K = 256; N = 1024; Nv = 1024; kx = w & 7; ny = w >> 3;
    } else {
        int u = tb - 2080; int mat = u >> 8, w = u & 255;
        W = W2 + (size_t)mat * DFF_ * D_; H = w2T + (size_t)mat * D_ * DFF_;
        K = 1024; N = 256; Nv = 256; kx = w & 31; ny = w >> 5;
    }
    const int k0 = kx * 32, n0 = ny * 32;
#pragma unroll
    for (int r = 0; r < 4; r++) {
        int n = n0 + tx;
        t[ty + 8 * r][tx] = (n < Nv) ? W[(size_t)(k0 + ty + 8 * r) * N + n] : 0.0f;
    }
    __syncthreads();
    if (!cls) {
#pragma unroll
        for (int r = 0; r < 4; r++)
            H[(size_t)(n0 + ty + 8 * r) * K + k0 + tx] =
                __float2half_rn(t[tx][ty + 8 * r]);
    } else {
#pragma unroll
        for (int r = 0; r < 4; r++) {
            float v = t[tx][ty + 8 * r];
            __half h = __float2half_rn(v);
            size_t o = (size_t)(n0 + ty + 8 * r) * 256 + k0 + tx;
            cH[o] = h;
            cL[o] = __float2half_rn(v - __half2float(h));
        }
    }
}

// ================== HMMA fp16 single-pass GEMM (3-stage) ==================
__device__ __forceinline__ void gemm_fill(
    uint32_t smU, int b, int kb,
    const __half* __restrict__ AHi, const __half* __restrict__ BHi,
    int K, int bm, int bn, int tid)
{
    const int k0 = kb * GKB;
    uint32_t aU = smU + b * BUFB;
    uint32_t bU = aU + APLANE;
#pragma unroll
    for (int i = 0; i < 4; i++) {
        int j   = tid + 256 * i;
        int row = j >> 3;
        int ch  = (j & 7) << 4;
        uint32_t off = swz128((uint32_t)(row * 128 + ch));
        cp_async16(aU + off, (const char*)AHi + ((size_t)(bm + row) * K + k0) * 2 + ch);
    }
#pragma unroll
    for (int i = 0; i < 2; i++) {
        int j   = tid + 256 * i;
        int row = j >> 3;
        int ch  = (j & 7) << 4;
        uint32_t off = swz128((uint32_t)(row * 128 + ch));
        cp_async16(bU + off, (const char*)BHi + ((size_t)(bn + row) * K + k0) * 2 + ch);
    }
}

__global__ __launch_bounds__(256, 3)
void gemm_tc(const __half* __restrict__ AHi,
             const __half* __restrict__ BHi,
             const float* __restrict__ bias,
             float* __restrict__ C,
             __half* __restrict__ CHi,
             int K, int N, int relu, int qcols)
{
    extern __shared__ char dsm_raw[];
    const int tid  = threadIdx.x;
    const int lane = tid & 31;
    const int wid  = tid >> 5;
    const int m0   = (wid >> 1) * 32;
    const int n0   = (wid & 1) * 32;
    const int bm   = blockIdx.y * GBM;
    const int bn   = blockIdx.x * GBN;
    const int nk   = K / GKB;

    uint32_t rawU = smem_u32(dsm_raw);
    uint32_t smU  = (rawU + 1023u) & ~1023u;

    float acc[2][4][4];
#pragma unroll
    for (int mi = 0; mi < 2; mi++)
#pragma unroll
        for (int ni = 0; ni < 4; ni++)
#pragma unroll
            for (int e = 0; e < 4; e++) acc[mi][ni][e] = 0.0f;

    gemm_fill(smU, 0, 0, AHi, BHi, K, bm, bn, tid);
    cp_commit();
    gemm_fill(smU, 1, 1, AHi, BHi, K, bm, bn, tid);
    cp_commit();

    const int a_row = m0 + (lane & 15);
    const int a_kb  = (lane >> 4) * 16;
    const int b_row = n0 + ((lane >> 4) << 3) + (lane & 7);
    const int b_kb  = ((lane >> 3) & 1) * 16;

    int bf = 0;
    for (int kb = 0; kb < nk; kb++) {
        if (kb + 1 < nk) cp_wait1(); else cp_wait0();
        __syncthreads();
        if (kb + 2 < nk) {
            int nb = bf + 2; if (nb >= 3) nb -= 3;
            gemm_fill(smU, nb, kb + 2, AHi, BHi, K, bm, bn, tid);
            cp_commit();
        }

        const uint32_t aU = smU + bf * BUFB;
        const uint32_t bU = aU + APLANE;
#pragma unroll
        for (int ks = 0; ks < 4; ks++) {
            const int kbase = ks * 32;
            uint32_t ah[2][4], bh[2][4];
#pragma unroll
            for (int mi = 0; mi < 2; mi++)
                ldsm_x4(ah[mi], aU + swz128((uint32_t)((a_row + mi * 16) * 128 + kbase + a_kb)));
#pragma unroll
            for (int bi = 0; bi < 2; bi++)
                ldsm_x4(bh[bi], bU + swz128((uint32_t)((b_row + bi * 16) * 128 + kbase + b_kb)));
#pragma unroll
            for (int mi = 0; mi < 2; mi++)
#pragma unroll
                for (int ni = 0; ni < 4; ni++)
                    mma_f16(acc[mi][ni], ah[mi],
                            bh[ni >> 1][(ni & 1) * 2], bh[ni >> 1][(ni & 1) * 2 + 1]);
        }
        if (++bf == 3) bf = 0;
    }

    const int gr = lane >> 2;
    const int gc = (lane & 3) * 2;
#pragma unroll
    for (int mi = 0; mi < 2; mi++) {
        int r0 = bm + m0 + mi * 16 + gr;
#pragma unroll
        for (int ni = 0; ni < 4; ni++) {
            int c = bn + n0 + ni * 8 + gc;
            int c0s = (c < N) ? c : N - 1;
            int c1s = (c + 1 < N) ? c + 1 : N - 1;
            float v00 = acc[mi][ni][0] + bias[c0s];
            float v01 = acc[mi][ni][1] + bias[c1s];
            float v10 = acc[mi][ni][2] + bias[c0s];
            float v11 = acc[mi][ni][3] + bias[c1s];
            if (relu) {
                v00 = fmaxf(v00, 0.f); v01 = fmaxf(v01, 0.f);
                v10 = fmaxf(v10, 0.f); v11 = fmaxf(v11, 0.f);
            }
            if (CHi) {
                if (c < qcols) {
                    v00 *= SCL2E; v01 *= SCL2E; v10 *= SCL2E; v11 *= SCL2E;
                }
                *(uint32_t*)(CHi + (size_t)r0 * N + c) = pack_f2h(v00, v01);
                *(uint32_t*)(CHi + (size_t)(r0 + 8) * N + c) = pack_f2h(v10, v11);
            } else if (c + 1 < N) {
                *(float2*)(C + (size_t)r0 * N + c) = make_float2(v00, v01);
                *(float2*)(C + (size_t)(r0 + 8) * N + c) = make_float2(v10, v11);
            } else if (c < N) {
                C[(size_t)r0 * N + c] = v00;
                C[(size_t)(r0 + 8) * N + c] = v10;
            }
        }
    }
}

// ============= classifier GEMM: 3-pass split precision ====================
__device__ __forceinline__ void cls_fill(
    uint32_t smU, int b, int kb,
    const __half* __restrict__ AHi, const __half* __restrict__ ALo,
    const __half* __restrict__ BHi, const __half* __restrict__ BLo,
    int K, int bm, int bn, int tid)
{
    const int k0 = kb * GKB;
    uint32_t aHiU = smU + b * CLS_BUFB;
    uint32_t aLoU = aHiU + APLANE;
    uint32_t bHiU = aHiU + 2 * APLANE;
    uint32_t bLoU = bHiU + BPLANE;
#pragma unroll
    for (int i = 0; i < 4; i++) {
        int j   = tid + 256 * i;
        int row = j >> 3;
        int ch  = (j & 7) << 4;
        uint32_t off = swz128((uint32_t)(row * 128 + ch));
        size_t srcb = ((size_t)(bm + row) * K + k0) * 2 + ch;
        cp_async16(aHiU + off, (const char*)AHi + srcb);
        cp_async16(aLoU + off, (const char*)ALo + srcb);
    }
#pragma unroll
    for (int i = 0; i < 2; i++) {
        int j   = tid + 256 * i;
        int row = j >> 3;
        int ch  = (j & 7) << 4;
        uint32_t off = swz128((uint32_t)(row * 128 + ch));
        size_t srcb = ((size_t)(bn + row) * K + k0) * 2 + ch;
        cp_async16(bHiU + off, (const char*)BHi + srcb);
        cp_async16(bLoU + off, (const char*)BLo + srcb);
    }
}

__global__ __launch_bounds__(256, 2)
void gemm_cls(const __half* __restrict__ AHi,
              const __half* __restrict__ ALo,
              const __half* __restrict__ BHi,
              const __half* __restrict__ BLo,
              const float* __restrict__ bias,
              float* __restrict__ C,
              int K, int N)
{
    extern __shared__ char dsm_raw[];
    const int tid  = threadIdx.x;
    const int lane = tid & 31;
    const int wid  = tid >> 5;
    const int m0   = (wid >> 1) * 32;
    const int n0   = (wid & 1) * 32;
    const int bm   = blockIdx.y * GBM;
    const int bn   = blockIdx.x * GBN;
    const int nk   = K / GKB;

    uint32_t rawU = smem_u32(dsm_raw);
    uint32_t smU  = (rawU + 1023u) & ~1023u;

    float acc[2][4][4];
#pragma unroll
    for (int mi = 0; mi < 2; mi++)
#pragma unroll
        for (int ni = 0; ni < 4; ni++)
#pragma unroll
            for (int e = 0; e < 4; e++) acc[mi][ni][e] = 0.0f;

    cls_fill(smU, 0, 0, AHi, ALo, BHi, BLo, K, bm, bn, tid);
    cp_commit();

    const int a_row = m0 + (lane & 15);
    const int a_kb  = (lane >> 4) * 16;
    const int b_row = n0 + ((lane >> 4) << 3) + (lane & 7);
    const int b_kb  = ((lane >> 3) & 1) * 16;

    for (int kb = 0; kb < nk; kb++) {
        const int b = kb & 1;
        if (kb + 1 < nk) {
            cls_fill(smU, b ^ 1, kb + 1, AHi, ALo, BHi, BLo, K, bm, bn, tid);
            cp_commit();
            cp_wait1();
        } else {
            cp_wait0();
        }
        __syncthreads();

        const uint32_t aU = smU + b * CLS_BUFB;
        const uint32_t bU = aU + 2 * APLANE;
#pragma unroll
        for (int ks = 0; ks < 4; ks++) {
            const int kbase = ks * 32;
            uint32_t ah[2][4], al[2][4], bh[2][4], bl[2][4];
#pragma unroll
            for (int mi = 0; mi < 2; mi++) {
                uint32_t off = swz128((uint32_t)((a_row + mi * 16) * 128 + kbase + a_kb));
                ldsm_x4(ah[mi], aU + off);
                ldsm_x4(al[mi], aU + APLANE + off);
            }
#pragma unroll
            for (int bi = 0; bi < 2; bi++) {
                uint32_t off = swz128((uint32_t)((b_row + bi * 16) * 128 + kbase + b_kb));
                ldsm_x4(bh[bi], bU + off);
                ldsm_x4(bl[bi], bU + BPLANE + off);
            }
#pragma unroll
            for (int mi = 0; mi < 2; mi++)
#pragma unroll
                for (int ni = 0; ni < 4; ni++) {
                    uint32_t h0 = bh[ni >> 1][(ni & 1) * 2];
                    uint32_t h1 = bh[ni >> 1][(ni & 1) * 2 + 1];
                    uint32_t l0 = bl[ni >> 1][(ni & 1) * 2];
                    uint32_t l1 = bl[ni >> 1][(ni & 1) * 2 + 1];
                    mma_f16(acc[mi][ni], ah[mi], h0, h1);
                    mma_f16(acc[mi][ni], ah[mi], l0, l1);
                    mma_f16(acc[mi][ni], al[mi], h0, h1);
                }
        }
        __syncthreads();
    }

    const int gr = lane >> 2;
    const int gc = (lane & 3) * 2;
#pragma unroll
    for (int mi = 0; mi < 2; mi++) {
        int r0 = bm + m0 + mi * 16 + gr;
#pragma unroll
        for (int ni = 0; ni < 4; ni++) {
            int c = bn + n0 + ni * 8 + gc;
            if (c + 1 < N) {
                *(float2*)(C + (size_t)r0 * N + c) =
                    make_float2(acc[mi][ni][0] + bias[c], acc[mi][ni][1] + bias[c + 1]);
                *(float2*)(C + (size_t)(r0 + 8) * N + c) =
                    make_float2(acc[mi][ni][2] + bias[c], acc[mi][ni][3] + bias[c + 1]);
            } else if (c < N) {
                C[(size_t)r0 * N + c] = acc[mi][ni][0] + bias[c];
                C[(size_t)(r0 + 8) * N + c] = acc[mi][ni][2] + bias[c];
            }
        }
    }
}

// ====== fused GEMM (N=256) + bias + residual + LayerNorm (3-stage) ========
// Residual prefetched from XH/XL planes at kernel start.
#define LN_BM 64
#define LN_AP 8192
#define LN_BP 32768
#define LN_STAGE (LN_AP + LN_BP)       // 40960
#define LN_SMEM (3*LN_STAGE + 1024)    // 123904

__device__ __forceinline__ void ln_fill(
    uint32_t smU, int b, int kb,
    const __half* __restrict__ AHi, const __half* __restrict__ BHi,
    int K, int bm, int tid)
{
    const int k0 = kb * GKB;
    uint32_t aU = smU + b * LN_STAGE;
    uint32_t bU = aU + LN_AP;
    {
        int row = tid >> 3;
        int ch  = (tid & 7) << 4;
        uint32_t off = swz128((uint32_t)(row * 128 + ch));
        cp_async16(aU + off, (const char*)AHi + ((size_t)(bm + row) * K + k0) * 2 + ch);
    }
#pragma unroll
    for (int i = 0; i < 4; i++) {
        int j   = tid + 512 * i;
        int row = j >> 3;
        int ch  = (j & 7) << 4;
        uint32_t off = swz128((uint32_t)(row * 128 + ch));
        cp_async16(bU + off, (const char*)BHi + ((size_t)row * K + k0) * 2 + ch);
    }
}

__global__ __launch_bounds__(512)
void gemm_ln(const __half* __restrict__ AHi,
             const __half* __restrict__ BHi,
             const float* __restrict__ bias,
             const float* __restrict__ g,
             const float* __restrict__ be,
             __half* __restrict__ XH,
             __half* __restrict__ XL,
             int K)
{
    extern __shared__ char dsm_raw[];
    __shared__ float redS[64][4], redQ[64][4];

    const int tid  = threadIdx.x;
    const int lane = tid & 31;
    const int wid  = tid >> 5;
    const int m0   = (wid >> 2) * 16;
    const int n0   = (wid & 3) * 64;
    const int bm   = blockIdx.x * LN_BM;
    const int nk   = K / GKB;

    uint32_t rawU = smem_u32(dsm_raw);
    uint32_t smU  = (rawU + 1023u) & ~1023u;

    float acc[8][4];
#pragma unroll
    for (int ni = 0; ni < 8; ni++)
#pragma unroll
        for (int e = 0; e < 4; e++) acc[ni][e] = 0.0f;

    ln_fill(smU, 0, 0, AHi, BHi, K, bm, tid);
    cp_commit();
    ln_fill(smU, 1, 1, AHi, BHi, K, bm, tid);
    cp_commit();

    // ---- prefetch residual (hi/lo planes) for this thread's output slots ----
    const int gr = lane >> 2;
    const int tg = lane & 3;
    const int rl0 = m0 + gr;
    const int rl1 = rl0 + 8;
    const size_t gb0 = (size_t)(bm + rl0) * D_;
    const size_t gb1 = (size_t)(bm + rl1) * D_;
    uint32_t rxh0[8], rxl0[8], rxh1[8], rxl1[8];
#pragma unroll
    for (int ni = 0; ni < 8; ni++) {
        int c = n0 + ni * 8 + tg * 2;
        rxh0[ni] = *(const uint32_t*)(XH + gb0 + c);
        rxl0[ni] = *(const uint32_t*)(XL + gb0 + c);
        rxh1[ni] = *(const uint32_t*)(XH + gb1 + c);
        rxl1[ni] = *(const uint32_t*)(XL + gb1 + c);
    }

    const int a_row = m0 + (lane & 15);
    const int a_kb  = (lane >> 4) * 16;
    const int b_rowL = ((lane >> 4) << 3) + (lane & 7);
    const int b_kb  = ((lane >> 3) & 1) * 16;

    int bf = 0;
    for (int kb = 0; kb < nk; kb++) {
        if (kb + 1 < nk) cp_wait1(); else cp_wait0();
        __syncthreads();
        if (kb + 2 < nk) {
            int nb = bf + 2; if (nb >= 3) nb -= 3;
            ln_fill(smU, nb, kb + 2, AHi, BHi, K, bm, tid);
            cp_commit();
        }

        const uint32_t aU = smU + bf * LN_STAGE;
        const uint32_t bU = aU + LN_AP;
#pragma unroll
        for (int ks = 0; ks < 4; ks++) {
            const int kbase = ks * 32;
            uint32_t ah[4], bh[4][4];
            ldsm_x4(ah, aU + swz128((uint32_t)(a_row * 128 + kbase + a_kb)));
#pragma unroll
            for (int bi = 0; bi < 4; bi++)
                ldsm_x4(bh[bi], bU + swz128((uint32_t)((n0 + bi * 16 + b_rowL) * 128 + kbase + b_kb)));
#pragma unroll
            for (int ni = 0; ni < 8; ni++)
                mma_f16(acc[ni], ah,
                        bh[ni >> 1][(ni & 1) * 2], bh[ni >> 1][(ni & 1) * 2 + 1]);
        }
        if (++bf == 3) bf = 0;
    }

    // ---- epilogue: bias + prefetched residual, row stats, LN, write ----
    const int nw = wid & 3;
    {
        float s0 = 0.f, q0 = 0.f, s1 = 0.f, q1 = 0.f;
#pragma unroll
        for (int ni = 0; ni < 8; ni++) {
            int c = n0 + ni * 8 + tg * 2;
            float2 bv = *(const float2*)(bias + c);
            float2 xh0 = h2f2(rxh0[ni]);
            float2 xl0 = h2f2(rxl0[ni]);
            float2 xh1 = h2f2(rxh1[ni]);
            float2 xl1 = h2f2(rxl1[ni]);
            acc[ni][0] += bv.x + xh0.x + xl0.x;
            acc[ni][1] += bv.y + xh0.y + xl0.y;
            acc[ni][2] += bv.x + xh1.x + xl1.x;
            acc[ni][3] += bv.y + xh1.y + xl1.y;
            s0 += acc[ni][0] + acc[ni][1];
            q0 += acc[ni][0] * acc[ni][0] + acc[ni][1] * acc[ni][1];
            s1 += acc[ni][2] + acc[ni][3];
            q1 += acc[ni][2] * acc[ni][2] + acc[ni][3] * acc[ni][3];
        }
#pragma unroll
        for (int o = 1; o <= 2; o <<= 1) {
            s0 += __shfl_xor_sync(0xFFFFFFFFu, s0, o);
            q0 += __shfl_xor_sync(0xFFFFFFFFu, q0, o);
            s1 += __shfl_xor_sync(0xFFFFFFFFu, s1, o);
            q1 += __shfl_xor_sync(0xFFFFFFFFu, q1, o);
        }
        if (tg == 0) {
            redS[rl0][nw] = s0; redQ[rl0][nw] = q0;
            redS[rl1][nw] = s1; redQ[rl1][nw] = q1;
        }
    }
    __syncthreads();

    {
        float S0 = redS[rl0][0] + redS[rl0][1] + redS[rl0][2] + redS[rl0][3];
        float Q0 = redQ[rl0][0] + redQ[rl0][1] + redQ[rl0][2] + redQ[rl0][3];
        float S1 = redS[rl1][0] + redS[rl1][1] + redS[rl1][2] + redS[rl1][3];
        float Q1 = redQ[rl1][0] + redQ[rl1][1] + redQ[rl1][2] + redQ[rl1][3];
        float mean0 = S0 * (1.0f / D_);
        float mean1 = S1 * (1.0f / D_);
        float r0 = rsqrtf(Q0 * (1.0f / D_) - mean0 * mean0 + 1e-5f);
        float r1 = rsqrtf(Q1 * (1.0f / D_) - mean1 * mean1 + 1e-5f);
#pragma unroll
        for (int ni = 0; ni < 8; ni++) {
            int c = n0 + ni * 8 + tg * 2;
            float2 gv = *(const float2*)(g + c);
            float2 bev = *(const float2*)(be + c);
            float o00 = (acc[ni][0] - mean0) * r0 * gv.x + bev.x;
            float o01 = (acc[ni][1] - mean0) * r0 * gv.y + bev.y;
            float o10 = (acc[ni][2] - mean1) * r1 * gv.x + bev.x;
            float o11 = (acc[ni][3] - mean1) * r1 * gv.y + bev.y;
            uint32_t hp, lp;
            split2h(o00, o01, hp, lp);
            *(uint32_t*)(XH + gb0 + c) = hp;
            *(uint32_t*)(XL + gb0 + c) = lp;
            split2h(o10, o11, hp, lp);
            *(uint32_t*)(XH + gb1 + c) = hp;
            *(uint32_t*)(XL + gb1 + c) = lp;
        }
    }
}

// ========== tensor-core causal flash attention (no-max softmax) ===========
// 64 queries/CTA, 4 warps x 16 rows, Q pre-scaled, x4 ldsm.
#define AT_PITCH 80
#define AT_Q 0
#define AT_KV 5120
#define AT_BUF 10240
#define AT_SMEM (AT_KV + 3*AT_BUF + 1024)

__device__ __forceinline__ void attn_fill_kv(
    uint32_t smU, int buf,
    const __half* __restrict__ Ph,
    size_t rowbase, int kt, int h, int tid)
{
    uint32_t base = smU + AT_KV + buf * AT_BUF;
#pragma unroll
    for (int i = 0; i < 2; i++) {
        int j = tid + 128 * i;
        int row = j >> 2, ch = (j & 3) * 16;
        size_t gk = ((rowbase + kt + row) * QKV_N + 256 + h * DH_) * 2 + ch;
        size_t gv = gk + 512;
        uint32_t d = row * AT_PITCH + ch;
        cp_async16(base + d,        (const char*)Ph + gk);
        cp_async16(base + 5120 + d, (const char*)Ph + gv);
    }
}

__global__ __launch_bounds__(128)
void attn_tc(const __half* __restrict__ Ph,
             __half* __restrict__ YH,
             const int* __restrict__ tsl)
{
    extern __shared__ char asmem_raw[];
    const int tid = threadIdx.x, lane = tid & 31, w = tid >> 5;
    const int qblk = (gridDim.x - 1) - blockIdx.x;   // longest-first
    const int h = blockIdx.y, b = blockIdx.z;
    const int q0 = qblk * 64;
    const int len = tsl[b];
    const int gr = lane >> 2, tg = lane & 3;
    uint32_t rawU = smem_u32(asmem_raw);
    const uint32_t smU = (rawU + 1023u) & ~1023u;
    const size_t rowbase = (size_t)b * S_;
    const int nt = qblk + 1;

#pragma unroll
    for (int i = 0; i < 2; i++) {
        int jj = tid + 128 * i;
        int row = jj >> 2, ch = (jj & 3) * 16;
        size_t src = ((rowbase + q0 + row) * QKV_N + h * DH_) * 2 + ch;
        cp_async16(smU + AT_Q + row * AT_PITCH + ch, (const char*)Ph + src);
    }
    attn_fill_kv(smU, 0, Ph, rowbase, 0, h, tid);
    cp_commit();
    if (nt > 1) {
        attn_fill_kv(smU, 1, Ph, rowbase, 64, h, tid);
        cp_commit();
        cp_wait1();
    } else {
        cp_wait0();
    }
    __syncthreads();

    uint32_t qf[2][4];
    {
        int r8 = (lane & 7) + ((lane >> 3) & 1) * 8;
        int cb = ((lane >> 4) & 1) * 16;
#pragma unroll
        for (int kk = 0; kk < 2; kk++)
            ldsm_x4(qf[kk], smU + AT_Q + (uint32_t)(w * 16 + r8) * AT_PITCH + kk * 32 + cb);
    }

    float o[4][4];
    float lrow[2] = {0.f, 0.f};
#pragma unroll
    for (int nd = 0; nd < 4; nd++)
#pragma unroll
        for (int e = 0; e < 4; e++) o[nd][e] = 0.f;

    const int qw0 = q0 + w * 16;
    const int l7 = lane & 7;
    const int khb = ((lane >> 3) & 1) * 16;
    const int nsel = (lane >> 4) & 1;
    const int l15 = lane & 15;

    int bf = 0;
    for (int t = 0; t < nt; t++) {
        const int kt = t * 64;
        if (t + 1 < nt) cp_wait1(); else cp_wait0();
        __syncthreads();
        if (t + 2 < nt) {
            int nb = bf + 2; if (nb >= 3) nb -= 3;
            attn_fill_kv(smU, nb, Ph, rowbase, kt + 128, h, tid);
            cp_commit();
        }

        const uint32_t kb = smU + AT_KV + bf * AT_BUF;
        const uint32_t vb = kb + 5120;

        float s[8][4];
#pragma unroll
        for (int ni = 0; ni < 8; ni++)
#pragma unroll
            for (int e = 0; e < 4; e++) s[ni][e] = 0.f;
#pragma unroll
        for (int kk = 0; kk < 2; kk++)
#pragma unroll
            for (int ni = 0; ni < 8; ni += 2) {
                uint32_t kf[4];
                ldsm_x4(kf, kb + (uint32_t)((ni + nsel) * 8 + l7) * AT_PITCH + kk * 32 + khb);
                mma_f16(s[ni],     qf[kk], kf[0], kf[1]);
                mma_f16(s[ni + 1], qf[kk], kf[2], kf[3]);
            }

        if (kt + 63 > qw0 || kt + 64 > len) {
            int r0 = qw0 + gr, r1 = r0 + 8;
#pragma unroll
            for (int ni = 0; ni < 8; ni++) {
                int c0 = kt + ni * 8 + tg * 2, c1 = c0 + 1;
                if (c0 > r0 || c0 >= len) s[ni][0] = -1e30f;
                if (c1 > r0 || c1 >= len) s[ni][1] = -1e30f;
                if (c0 > r1 || c0 >= len) s[ni][2] = -1e30f;
                if (c1 > r1 || c1 >= len) s[ni][3] = -1e30f;
            }
        }

#pragma unroll
        for (int ni = 0; ni < 8; ni++) {
            float p0 = exp2f(s[ni][0]);
            float p1 = exp2f(s[ni][1]);
            float p2 = exp2f(s[ni][2]);
            float p3 = exp2f(s[ni][3]);
            s[ni][0] = p0; s[ni][1] = p1; s[ni][2] = p2; s[ni][3] = p3;
            lrow[0] += p0 + p1;
            lrow[1] += p2 + p3;
        }

#pragma unroll
        for (int j = 0; j < 4; j++) {
            uint32_t pa[4];
            pa[0] = pack_f2h(s[2*j][0],   s[2*j][1]);
            pa[1] = pack_f2h(s[2*j][2],   s[2*j][3]);
            pa[2] = pack_f2h(s[2*j+1][0], s[2*j+1][1]);
            pa[3] = pack_f2h(s[2*j+1][2], s[2*j+1][3]);
#pragma unroll
            for (int nd = 0; nd < 4; nd += 2) {
                uint32_t vf[4];
                ldsm_x4t(vf, vb + (uint32_t)(16 * j + l15) * AT_PITCH + (nd + nsel) * 16);
                mma_f16(o[nd],     pa, vf[0], vf[1]);
                mma_f16(o[nd + 1], pa, vf[2], vf[3]);
            }
        }
        if (++bf == 3) bf = 0;
    }

#pragma unroll
    for (int hh = 0; hh < 2; hh++) {
        float v = lrow[hh];
        v += __shfl_xor_sync(0xFFFFFFFFu, v, 1);
        v += __shfl_xor_sync(0xFFFFFFFFu, v, 2);
        lrow[hh] = v;
    }
    int r0 = qw0 + gr, r1 = r0 + 8;
    float inv0 = (r0 < len && lrow[0] > 0.f) ? 1.0f / lrow[0] : 0.f;
    float inv1 = (r1 < len && lrow[1] > 0.f) ? 1.0f / lrow[1] : 0.f;
#pragma unroll
    for (int nd = 0; nd < 4; nd++) {
        int col = h * DH_ + nd * 8 + tg * 2;
        *(uint32_t*)(YH + (rowbase + r0) * D_ + col) = pack_f2h(o[nd][0] * inv0, o[nd][1] * inv0);
        *(uint32_t*)(YH + (rowbase + r1) * D_ + col) = pack_f2h(o[nd][2] * inv1, o[nd][3] * inv1);
    }
}

// =========================== launcher ====================================
extern "C" void kernel_launch(void* const* d_in, const int* in_sizes, int n_in,
                              void* d_out, int out_size)
{
    const int*   ids = (const int*)  d_in[0];
    const int*   tsl = (const int*)  d_in[1];
    const float* emb = (const float*)d_in[2];
    const float* Wq  = (const float*)d_in[3];
    const float* bq  = (const float*)d_in[4];
    const float* Wk  = (const float*)d_in[5];
    const float* bk  = (const float*)d_in[6];
    const float* Wv  = (const float*)d_in[7];
    const float* bv  = (const float*)d_in[8];
    const float* Wo  = (const float*)d_in[9];
    const float* bo  = (const float*)d_in[10];
    const float* W1  = (const float*)d_in[11];
    const float* b1  = (const float*)d_in[12];
    const float* W2  = (const float*)d_in[13];
    const float* b2  = (const float*)d_in[14];
    const float* g1  = (const float*)d_in[15];
    const float* be1 = (const float*)d_in[16];
    const float* g2  = (const float*)d_in[17];
    const float* be2 = (const float*)d_in[18];
    const float* Wc  = (const float*)d_in[19];
    const float* bc  = (const float*)d_in[20];
    float* out = (float*)d_out;

    float *bqkv;
    cudaGetSymbolAddress((void**)&bqkv, g_bqkv);

    __half *xh, *xl, *yh, *ffh, *qkvh;
    cudaGetSymbolAddress((void**)&xh,  g_xh);
    cudaGetSymbolAddress((void**)&xl,  g_xl);
    cudaGetSymbolAddress((void**)&yh,  g_yh);
    cudaGetSymbolAddress((void**)&ffh, g_ffh);
    cudaGetSymbolAddress((void**)&qkvh, g_qkvh);

    __half *qkvT, *oT, *w1T, *w2T, *wch, *wcl;
    cudaGetSymbolAddress((void**)&qkvT, g_qkvT);
    cudaGetSymbolAddress((void**)&oT,   g_oT);
    cudaGetSymbolAddress((void**)&w1T,  g_1T);
    cudaGetSymbolAddress((void**)&w2T,  g_2T);
    cudaGetSymbolAddress((void**)&wch,  g_cT_hi);
    cudaGetSymbolAddress((void**)&wcl,  g_cT_lo);

    cudaFuncSetAttribute((const void*)gemm_tc,
                         cudaFuncAttributeMaxDynamicSharedMemorySize, GEMM_SMEM);
    cudaFuncSetAttribute((const void*)gemm_cls,
                         cudaFuncAttributeMaxDynamicSharedMemorySize, CLS_SMEM);
    cudaFuncSetAttribute((const void*)gemm_ln,
                         cudaFuncAttributeMaxDynamicSharedMemorySize, LN_SMEM);
    cudaFuncSetAttribute((const void*)attn_tc,
                         cudaFuncAttributeMaxDynamicSharedMemorySize, AT_SMEM);

    prep_kernel<<<PREP_CONV + S_ + 3 * L_, dim3(32, 8)>>>(
        Wq, Wk, Wv, Wo, Wc, W1, W2, qkvT, oT, wch, wcl, w1T, w2T,
        ids, emb, bq, bk, bv, bqkv, xh, xl);

    dim3 gQKV(QKV_N / GBN, M_TOK / GBM);
    dim3 gF  (DFF_ / GBN,  M_TOK / GBM);
    dim3 gC  (2,           M_TOK / GBM);
    const int gLN = M_TOK / LN_BM;   // 128

    for (int l = 0; l < L_; l++) {
        size_t qoff  = (size_t)l * QKV_N * D_;
        size_t ooff  = (size_t)l * D_ * D_;
        size_t w1off = (size_t)l * DFF_ * D_;

        gemm_tc<<<gQKV, 256, GEMM_SMEM>>>(xh, qkvT + qoff,
                                          bqkv + l * QKV_N, 0, qkvh, D_, QKV_N, 0, 256);
        attn_tc<<<dim3(S_ / 64, H_, B_), 128, AT_SMEM>>>(qkvh, yh, tsl);

        gemm_ln<<<gLN, 512, LN_SMEM>>>(yh, oT + ooff,
                                       bo + l * D_, g1 + l * D_, be1 + l * D_,
                                       xh, xl, D_);

        gemm_tc<<<gF, 256, GEMM_SMEM>>>(xh, w1T + w1off,
                                        b1 + l * DFF_, 0, ffh, D_, DFF_, 1, 0);

        gemm_ln<<<gLN, 512, LN_SMEM>>>(ffh, w2T + w1off,
                                       b2 + l * D_, g2 + l * D_, be2 + l * D_,
                                       xh, xl, DFF_);
    }

    gemm_cls<<<gC, 256, CLS_SMEM>>>(xh, xl, wch, wcl, bc, out, D_, V_);
}